// round 11
// baseline (speedup 1.0000x reference)
#include <cuda_runtime.h>
#include <cuda_fp16.h>
#include <mma.h>
#include <math.h>

using namespace nvcuda;

#define N_NODES 40000
#define E_EDGES 640000
#define IN_F 128
#define OUT_F 32
#define HEADS 8
#define MCOLS (HEADS * OUT_F)   // 256

// Scratch (static device globals; no allocation allowed).
__device__ __align__(16) __half g_Mh[N_NODES * MCOLS];   // h @ W_msg[:128] fp16
__device__ __align__(16) __half g_h16[N_NODES * IN_F];   // h in fp16 (10.2 MB)
__device__ __align__(16) __half g_W16[IN_F * MCOLS];     // W_msg[:128] fp16 (64 KB)
__device__ __align__(16) float g_asrc[N_NODES * HEADS];
__device__ __align__(16) float g_adst[N_NODES * HEADS];
__device__ __align__(16) float g_sum[N_NODES * HEADS];   // softmax denominators
__device__ __align__(16) float g_attn[E_EDGES * HEADS];  // exp(score), edge order
__device__ __align__(16) float g_csrc[IN_F * HEADS];
__device__ __align__(16) float g_cdst[IN_F * HEADS];

// ---------------------------------------------------------------------------
__global__ void k_init(float* __restrict__ out) {
    int i = blockIdx.x * blockDim.x + threadIdx.x;
    if (i < N_NODES * OUT_F) out[i] = 0.f;
    if (i < N_NODES * HEADS) g_sum[i] = 0.f;
}

// ---------------------------------------------------------------------------
// fold W_node with attention vectors: c[i,h] = sum_f W_node[i, h*32+f] * att[h,f]
__global__ void k_coef(const float* __restrict__ Wn,
                       const float* __restrict__ att_s,
                       const float* __restrict__ att_d) {
    int t = threadIdx.x;             // 1024 threads: t = i*8 + h
    int i = t >> 3, hh = t & 7;
    float s1 = 0.f, s2 = 0.f;
    #pragma unroll
    for (int f = 0; f < OUT_F; f++) {
        float w = Wn[i * MCOLS + hh * OUT_F + f];
        s1 += w * att_s[hh * OUT_F + f];
        s2 += w * att_d[hh * OUT_F + f];
    }
    g_csrc[t] = s1;
    g_cdst[t] = s2;
}

// ---------------------------------------------------------------------------
// convert W_msg[:128,:] to fp16 (32768 elems)
__global__ void k_cvtW(const float* __restrict__ Wm) {
    int i = blockIdx.x * blockDim.x + threadIdx.x;   // 0..16383, x2 floats
    float2 v = *(const float2*)(Wm + i * 2);
    *(__half2*)(g_W16 + i * 2) = __floats2half2_rn(v.x, v.y);
}

// ---------------------------------------------------------------------------
// per-node attention pre-scores, tiled; also emits h in fp16 (from the same
// registers) for the tensor-core GEMM.
__global__ void __launch_bounds__(256) k_anode(const float* __restrict__ h) {
    __shared__ float hs[64][132];
    __shared__ float cs[IN_F * HEADS];
    __shared__ float cd[IN_F * HEADS];
    int tid = threadIdx.x;
    int n0 = blockIdx.x * 64;        // 625 blocks exact
    for (int i = tid; i < IN_F * HEADS; i += 256) {
        cs[i] = g_csrc[i];
        cd[i] = g_cdst[i];
    }
    int r = tid >> 2, cb = (tid & 3) * 32;
    const float* hr = h + (size_t)(n0 + r) * IN_F + cb;
    float4 v[8];
    #pragma unroll
    for (int q = 0; q < 8; q++) {
        v[q] = *(const float4*)(hr + q * 4);
        *(float4*)&hs[r][cb + q * 4] = v[q];
    }
    // fp16 copy of this thread's 32 h values (64B, aligned)
    {
        __half2 t16[16];
        #pragma unroll
        for (int q = 0; q < 8; q++) {
            t16[q * 2]     = __floats2half2_rn(v[q].x, v[q].y);
            t16[q * 2 + 1] = __floats2half2_rn(v[q].z, v[q].w);
        }
        __half* dst = g_h16 + (size_t)(n0 + r) * IN_F + cb;
        #pragma unroll
        for (int q = 0; q < 4; q++)
            *(uint4*)(dst + q * 8) = ((uint4*)t16)[q];
    }
    __syncthreads();
    #pragma unroll
    for (int rep = 0; rep < 2; rep++) {
        int o = tid + rep * 256;     // 0..511
        int n = o >> 3, hh = o & 7;
        float s1 = 0.f, s2 = 0.f;
        #pragma unroll 8
        for (int i = 0; i < IN_F; i++) {
            float hv = hs[n][i];
            s1 += hv * cs[i * HEADS + hh];
            s2 += hv * cd[i * HEADS + hh];
        }
        g_asrc[(n0 + n) * HEADS + hh] = s1;
        g_adst[(n0 + n) * HEADS + hh] = s2;
    }
}

// ---------------------------------------------------------------------------
// Tensor-core GEMM: M = h16 @ W16, fp16 out. Inputs already fp16: tile loads
// are pure 16B copies (no cvt, low regs -> high occupancy for latency hiding).
__global__ void __launch_bounds__(256) k_gemm() {
    __shared__ __align__(32) __half Ah[64][48];
    __shared__ __align__(32) __half Bh[32][272];
    __shared__ __align__(16) float Cst[8][16][16];
    int tid = threadIdx.x;
    int wid = tid >> 5, lane = tid & 31;
    int wm = wid >> 2;
    int wn = wid & 3;
    int m0 = blockIdx.x * 64;

    wmma::fragment<wmma::accumulator, 16, 16, 16, float> c[2][4];
    #pragma unroll
    for (int i = 0; i < 2; i++)
        #pragma unroll
        for (int j = 0; j < 4; j++) wmma::fill_fragment(c[i][j], 0.f);

    int ar = tid >> 2;               // 0..63
    int ac = (tid & 3) * 8;          // 0,8,16,24 (halves)
    int br = tid >> 3;               // 0..31
    int bc = (tid & 7) * 32;         // 0..224 (halves)

    for (int k0 = 0; k0 < IN_F; k0 += 32) {
        *(uint4*)&Ah[ar][ac] =
            *(const uint4*)(g_h16 + (size_t)(m0 + ar) * IN_F + k0 + ac);
        const __half* bg = g_W16 + (size_t)(k0 + br) * MCOLS + bc;
        #pragma unroll
        for (int q = 0; q < 4; q++)
            *(uint4*)&Bh[br][bc + q * 8] = *(const uint4*)(bg + q * 8);
        __syncthreads();
        #pragma unroll
        for (int kk = 0; kk < 32; kk += 16) {
            wmma::fragment<wmma::matrix_a, 16, 16, 16, __half, wmma::row_major> af[2];
            wmma::fragment<wmma::matrix_b, 16, 16, 16, __half, wmma::row_major> bf[4];
            #pragma unroll
            for (int i = 0; i < 2; i++)
                wmma::load_matrix_sync(af[i], &Ah[wm * 32 + i * 16][kk], 48);
            #pragma unroll
            for (int j = 0; j < 4; j++)
                wmma::load_matrix_sync(bf[j], &Bh[kk][wn * 64 + j * 16], 272);
            #pragma unroll
            for (int i = 0; i < 2; i++)
                #pragma unroll
                for (int j = 0; j < 4; j++)
                    wmma::mma_sync(c[i][j], af[i], bf[j], c[i][j]);
        }
        __syncthreads();
    }
    int rr = lane >> 1, cc = (lane & 1) * 8;
    #pragma unroll
    for (int i = 0; i < 2; i++)
        #pragma unroll
        for (int j = 0; j < 4; j++) {
            wmma::store_matrix_sync(&Cst[wid][0][0], c[i][j], 16, wmma::mem_row_major);
            __syncwarp();
            const float* sp = &Cst[wid][rr][cc];
            __half2 hv[4];
            #pragma unroll
            for (int q = 0; q < 4; q++)
                hv[q] = __floats2half2_rn(sp[q * 2], sp[q * 2 + 1]);
            int grow = m0 + wm * 32 + i * 16 + rr;
            int gcol = wn * 64 + j * 16 + cc;
            *(uint4*)(g_Mh + (size_t)grow * MCOLS + gcol) = *(uint4*)hv;
            __syncwarp();
        }
}

// ---------------------------------------------------------------------------
// edge pass: score -> leaky relu -> exp (no max shift; bounded scores),
// store p coalesced in edge order; denominator via two v4 vector reductions.
__global__ void k_score(const int* __restrict__ ei, const float* __restrict__ ef,
                        const float* __restrict__ We) {
    int e = blockIdx.x * blockDim.x + threadIdx.x;
    if (e >= E_EDGES) return;
    int s = ei[e];
    int d = ei[E_EDGES + e];
    float x = ef[e];

    float4 sa0 = *(const float4*)&g_asrc[s * HEADS];
    float4 sa1 = *(const float4*)&g_asrc[s * HEADS + 4];
    float4 da0 = *(const float4*)&g_adst[d * HEADS];
    float4 da1 = *(const float4*)&g_adst[d * HEADS + 4];
    float sv[8] = {sa0.x, sa0.y, sa0.z, sa0.w, sa1.x, sa1.y, sa1.z, sa1.w};
    float dv[8] = {da0.x, da0.y, da0.z, da0.w, da1.x, da1.y, da1.z, da1.w};

    float p[8];
    #pragma unroll
    for (int hh = 0; hh < HEADS; hh++) {
        float a = sv[hh] + dv[hh] + x * __ldg(&We[hh]);
        a = (a > 0.f) ? a : 0.2f * a;          // leaky relu
        p[hh] = __expf(a);
    }
    float* ap = &g_attn[(size_t)e * HEADS];
    *(float4*)ap       = make_float4(p[0], p[1], p[2], p[3]);
    *(float4*)(ap + 4) = make_float4(p[4], p[5], p[6], p[7]);

    float* sp = &g_sum[d * HEADS];             // 32B-aligned (d*8 floats)
    asm volatile("red.global.add.v4.f32 [%0], {%1, %2, %3, %4};"
                 :: "l"(sp), "f"(p[0]), "f"(p[1]), "f"(p[2]), "f"(p[3])
                 : "memory");
    asm volatile("red.global.add.v4.f32 [%0], {%1, %2, %3, %4};"
                 :: "l"(sp + 4), "f"(p[4]), "f"(p[5]), "f"(p[6]), "f"(p[7])
                 : "memory");
}

// ---------------------------------------------------------------------------
// final pass: warp per edge. lane = (head hh = lane/4, cluster c = lane%4).
// One LDG.128 per lane covers M[s,hh,c*8..c*8+7]; head reduction via 3
// shfl_xor stages; lanes 0..3 emit two red.global.add.v4 each.
__global__ void __launch_bounds__(512) k_out(const int* __restrict__ ei,
                                             const float* __restrict__ ef,
                                             const float* __restrict__ Wm,
                                             float* __restrict__ out) {
    int gw = (blockIdx.x * blockDim.x + threadIdx.x) >> 5;
    int lane = threadIdx.x & 31;
    if (gw >= E_EDGES) return;
    int s = ei[gw];
    int d = ei[E_EDGES + gw];
    float x = ef[gw];
    int hh = lane >> 2;          // head 0..7
    int cc = lane & 3;           // feature cluster 0..3 (8 feats each)

    // alpha for lanes<8, then broadcast alpha[hh] to every lane
    float al = 0.f;
    if (lane < HEADS) {
        float sm = g_sum[d * HEADS + lane];
        al = __fdividef(g_attn[(size_t)gw * HEADS + lane], fmaxf(sm, 1e-12f));
    }
    float a = __shfl_sync(0xffffffffu, al, hh);

    // one 16B load: M[s, hh, cc*8 .. cc*8+7]  (warp covers the 512B row)
    const __half* Mp = g_Mh + (size_t)s * MCOLS + hh * OUT_F + cc * 8;
    uint4 mw = *(const uint4*)Mp;
    __half2* mh = (__half2*)&mw;
    // W_msg edge-feat row, same 8 features
    const float* Wl = Wm + (size_t)IN_F * MCOLS + hh * OUT_F + cc * 8;
    float4 w0 = __ldg((const float4*)Wl);
    float4 w1 = __ldg((const float4*)(Wl + 4));

    float cb[8];
    float2 m;
    m = __half22float2(mh[0]); cb[0] = a * fmaf(x, w0.x, m.x); cb[1] = a * fmaf(x, w0.y, m.y);
    m = __half22float2(mh[1]); cb[2] = a * fmaf(x, w0.z, m.x); cb[3] = a * fmaf(x, w0.w, m.y);
    m = __half22float2(mh[2]); cb[4] = a * fmaf(x, w1.x, m.x); cb[5] = a * fmaf(x, w1.y, m.y);
    m = __half22float2(mh[3]); cb[6] = a * fmaf(x, w1.z, m.x); cb[7] = a * fmaf(x, w1.w, m.y);

    // reduce over heads: lanes {cc, cc+4, ..., cc+28}
    #pragma unroll
    for (int off = 4; off <= 16; off <<= 1)
        #pragma unroll
        for (int j = 0; j < 8; j++)
            cb[j] += __shfl_xor_sync(0xffffffffu, cb[j], off);

    if (lane < 4) {
        float* op = out + (size_t)d * OUT_F + cc * 8;
        asm volatile("red.global.add.v4.f32 [%0], {%1, %2, %3, %4};"
                     :: "l"(op), "f"(cb[0] * 0.125f), "f"(cb[1] * 0.125f),
                        "f"(cb[2] * 0.125f), "f"(cb[3] * 0.125f) : "memory");
        asm volatile("red.global.add.v4.f32 [%0], {%1, %2, %3, %4};"
                     :: "l"(op + 4), "f"(cb[4] * 0.125f), "f"(cb[5] * 0.125f),
                        "f"(cb[6] * 0.125f), "f"(cb[7] * 0.125f) : "memory");
    }
}

// ---------------------------------------------------------------------------
extern "C" void kernel_launch(void* const* d_in, const int* in_sizes, int n_in,
                              void* d_out, int out_size) {
    const float* h   = (const float*)d_in[0];
    const int*   ei  = (const int*)d_in[1];
    const float* ef  = (const float*)d_in[2];
    const float* Wn  = (const float*)d_in[3];
    const float* We  = (const float*)d_in[4];
    const float* Asw = (const float*)d_in[5];
    const float* Adw = (const float*)d_in[6];
    const float* Wm  = (const float*)d_in[7];
    float* out = (float*)d_out;

    k_init<<<(N_NODES * OUT_F + 255) / 256, 256>>>(out);
    k_coef<<<1, 1024>>>(Wn, Asw, Adw);
    k_cvtW<<<(IN_F * MCOLS / 2 + 255) / 256, 256>>>(Wm);
    k_anode<<<N_NODES / 64, 256>>>(h);
    k_gemm<<<N_NODES / 64, 256>>>();
    k_score<<<(E_EDGES + 255) / 256, 256>>>(ei, ef, We);
    k_out<<<(E_EDGES * 32 + 511) / 512, 512>>>(ei, ef, Wm, out);
}

// round 12
// speedup vs baseline: 1.1958x; 1.1958x over previous
#include <cuda_runtime.h>
#include <cuda_fp16.h>
#include <mma.h>
#include <math.h>

using namespace nvcuda;

#define N_NODES 40000
#define E_EDGES 640000
#define IN_F 128
#define OUT_F 32
#define HEADS 8
#define MCOLS (HEADS * OUT_F)   // 256

// Scratch (static device globals; no allocation allowed).
__device__ __align__(16) __half g_Mh[N_NODES * MCOLS];   // h @ W_msg[:128] fp16
__device__ __align__(16) __half g_h16[N_NODES * IN_F];   // h in fp16 (10.2 MB)
__device__ __align__(16) __half g_W16[IN_F * MCOLS];     // W_msg[:128] fp16 (64 KB)
__device__ __align__(16) float g_asrc[N_NODES * HEADS];
__device__ __align__(16) float g_adst[N_NODES * HEADS];
__device__ __align__(16) float g_sum[N_NODES * HEADS];   // softmax denominators
__device__ __align__(16) float g_attn[E_EDGES * HEADS];  // exp(score), edge order
__device__ __align__(16) float g_csrc[IN_F * HEADS];
__device__ __align__(16) float g_cdst[IN_F * HEADS];

// ---------------------------------------------------------------------------
__global__ void k_init(float* __restrict__ out) {
    int i = blockIdx.x * blockDim.x + threadIdx.x;
    if (i < N_NODES * OUT_F) out[i] = 0.f;
    if (i < N_NODES * HEADS) g_sum[i] = 0.f;
}

// ---------------------------------------------------------------------------
// fold W_node with attention vectors: c[i,h] = sum_f W_node[i, h*32+f] * att[h,f]
__global__ void k_coef(const float* __restrict__ Wn,
                       const float* __restrict__ att_s,
                       const float* __restrict__ att_d) {
    int t = threadIdx.x;             // 1024 threads: t = i*8 + h
    int i = t >> 3, hh = t & 7;
    float s1 = 0.f, s2 = 0.f;
    #pragma unroll
    for (int f = 0; f < OUT_F; f++) {
        float w = Wn[i * MCOLS + hh * OUT_F + f];
        s1 += w * att_s[hh * OUT_F + f];
        s2 += w * att_d[hh * OUT_F + f];
    }
    g_csrc[t] = s1;
    g_cdst[t] = s2;
}

// ---------------------------------------------------------------------------
// convert W_msg[:128,:] to fp16 (32768 elems)
__global__ void k_cvtW(const float* __restrict__ Wm) {
    int i = blockIdx.x * blockDim.x + threadIdx.x;   // 0..16383, x2 floats
    float2 v = *(const float2*)(Wm + i * 2);
    *(__half2*)(g_W16 + i * 2) = __floats2half2_rn(v.x, v.y);
}

// ---------------------------------------------------------------------------
// per-node attention pre-scores, tiled; also emits h in fp16 (from the same
// registers) for the tensor-core GEMM.
__global__ void __launch_bounds__(256) k_anode(const float* __restrict__ h) {
    __shared__ float hs[64][132];
    __shared__ float cs[IN_F * HEADS];
    __shared__ float cd[IN_F * HEADS];
    int tid = threadIdx.x;
    int n0 = blockIdx.x * 64;        // 625 blocks exact
    for (int i = tid; i < IN_F * HEADS; i += 256) {
        cs[i] = g_csrc[i];
        cd[i] = g_cdst[i];
    }
    int r = tid >> 2, cb = (tid & 3) * 32;
    const float* hr = h + (size_t)(n0 + r) * IN_F + cb;
    float4 v[8];
    #pragma unroll
    for (int q = 0; q < 8; q++) {
        v[q] = *(const float4*)(hr + q * 4);
        *(float4*)&hs[r][cb + q * 4] = v[q];
    }
    // fp16 copy of this thread's 32 h values (64B, aligned)
    {
        __half2 t16[16];
        #pragma unroll
        for (int q = 0; q < 8; q++) {
            t16[q * 2]     = __floats2half2_rn(v[q].x, v[q].y);
            t16[q * 2 + 1] = __floats2half2_rn(v[q].z, v[q].w);
        }
        __half* dst = g_h16 + (size_t)(n0 + r) * IN_F + cb;
        #pragma unroll
        for (int q = 0; q < 4; q++)
            *(uint4*)(dst + q * 8) = ((uint4*)t16)[q];
    }
    __syncthreads();
    #pragma unroll
    for (int rep = 0; rep < 2; rep++) {
        int o = tid + rep * 256;     // 0..511
        int n = o >> 3, hh = o & 7;
        float s1 = 0.f, s2 = 0.f;
        #pragma unroll 8
        for (int i = 0; i < IN_F; i++) {
            float hv = hs[n][i];
            s1 += hv * cs[i * HEADS + hh];
            s2 += hv * cd[i * HEADS + hh];
        }
        g_asrc[(n0 + n) * HEADS + hh] = s1;
        g_adst[(n0 + n) * HEADS + hh] = s2;
    }
}

// ---------------------------------------------------------------------------
// Tensor-core GEMM: M = h16 @ W16, fp16 out. Inputs already fp16: tile loads
// are pure 16B copies (no cvt, low regs -> high occupancy for latency hiding).
__global__ void __launch_bounds__(256) k_gemm() {
    __shared__ __align__(32) __half Ah[64][48];
    __shared__ __align__(32) __half Bh[32][272];
    __shared__ __align__(16) float Cst[8][16][16];
    int tid = threadIdx.x;
    int wid = tid >> 5, lane = tid & 31;
    int wm = wid >> 2;
    int wn = wid & 3;
    int m0 = blockIdx.x * 64;

    wmma::fragment<wmma::accumulator, 16, 16, 16, float> c[2][4];
    #pragma unroll
    for (int i = 0; i < 2; i++)
        #pragma unroll
        for (int j = 0; j < 4; j++) wmma::fill_fragment(c[i][j], 0.f);

    int ar = tid >> 2;               // 0..63
    int ac = (tid & 3) * 8;          // 0,8,16,24 (halves)
    int br = tid >> 3;               // 0..31
    int bc = (tid & 7) * 32;         // 0..224 (halves)

    for (int k0 = 0; k0 < IN_F; k0 += 32) {
        *(uint4*)&Ah[ar][ac] =
            *(const uint4*)(g_h16 + (size_t)(m0 + ar) * IN_F + k0 + ac);
        const __half* bg = g_W16 + (size_t)(k0 + br) * MCOLS + bc;
        #pragma unroll
        for (int q = 0; q < 4; q++)
            *(uint4*)&Bh[br][bc + q * 8] = *(const uint4*)(bg + q * 8);
        __syncthreads();
        #pragma unroll
        for (int kk = 0; kk < 32; kk += 16) {
            wmma::fragment<wmma::matrix_a, 16, 16, 16, __half, wmma::row_major> af[2];
            wmma::fragment<wmma::matrix_b, 16, 16, 16, __half, wmma::row_major> bf[4];
            #pragma unroll
            for (int i = 0; i < 2; i++)
                wmma::load_matrix_sync(af[i], &Ah[wm * 32 + i * 16][kk], 48);
            #pragma unroll
            for (int j = 0; j < 4; j++)
                wmma::load_matrix_sync(bf[j], &Bh[kk][wn * 64 + j * 16], 272);
            #pragma unroll
            for (int i = 0; i < 2; i++)
                #pragma unroll
                for (int j = 0; j < 4; j++)
                    wmma::mma_sync(c[i][j], af[i], bf[j], c[i][j]);
        }
        __syncthreads();
    }
    int rr = lane >> 1, cc = (lane & 1) * 8;
    #pragma unroll
    for (int i = 0; i < 2; i++)
        #pragma unroll
        for (int j = 0; j < 4; j++) {
            wmma::store_matrix_sync(&Cst[wid][0][0], c[i][j], 16, wmma::mem_row_major);
            __syncwarp();
            const float* sp = &Cst[wid][rr][cc];
            __half2 hv[4];
            #pragma unroll
            for (int q = 0; q < 4; q++)
                hv[q] = __floats2half2_rn(sp[q * 2], sp[q * 2 + 1]);
            int grow = m0 + wm * 32 + i * 16 + rr;
            int gcol = wn * 64 + j * 16 + cc;
            *(uint4*)(g_Mh + (size_t)grow * MCOLS + gcol) = *(uint4*)hv;
            __syncwarp();
        }
}

// ---------------------------------------------------------------------------
// edge pass: score -> leaky relu -> exp (no max shift; bounded scores),
// store p coalesced in edge order; denominator via two v4 vector reductions.
__global__ void k_score(const int* __restrict__ ei, const float* __restrict__ ef,
                        const float* __restrict__ We) {
    int e = blockIdx.x * blockDim.x + threadIdx.x;
    if (e >= E_EDGES) return;
    int s = ei[e];
    int d = ei[E_EDGES + e];
    float x = ef[e];

    float4 sa0 = *(const float4*)&g_asrc[s * HEADS];
    float4 sa1 = *(const float4*)&g_asrc[s * HEADS + 4];
    float4 da0 = *(const float4*)&g_adst[d * HEADS];
    float4 da1 = *(const float4*)&g_adst[d * HEADS + 4];
    float sv[8] = {sa0.x, sa0.y, sa0.z, sa0.w, sa1.x, sa1.y, sa1.z, sa1.w};
    float dv[8] = {da0.x, da0.y, da0.z, da0.w, da1.x, da1.y, da1.z, da1.w};

    float p[8];
    #pragma unroll
    for (int hh = 0; hh < HEADS; hh++) {
        float a = sv[hh] + dv[hh] + x * __ldg(&We[hh]);
        a = (a > 0.f) ? a : 0.2f * a;          // leaky relu
        p[hh] = __expf(a);
    }
    float* ap = &g_attn[(size_t)e * HEADS];
    *(float4*)ap       = make_float4(p[0], p[1], p[2], p[3]);
    *(float4*)(ap + 4) = make_float4(p[4], p[5], p[6], p[7]);

    float* sp = &g_sum[d * HEADS];             // 32B-aligned (d*8 floats)
    asm volatile("red.global.add.v4.f32 [%0], {%1, %2, %3, %4};"
                 :: "l"(sp), "f"(p[0]), "f"(p[1]), "f"(p[2]), "f"(p[3])
                 : "memory");
    asm volatile("red.global.add.v4.f32 [%0], {%1, %2, %3, %4};"
                 :: "l"(sp + 4), "f"(p[4]), "f"(p[5]), "f"(p[6]), "f"(p[7])
                 : "memory");
}

// ---------------------------------------------------------------------------
// final pass (R10 version — measured fastest): warp per edge, lane = output
// feature. contrib[f] = sum_h alpha[h] * (M[src,h,f] + ef * W_msg[128,h*32+f])
__global__ void __launch_bounds__(512) k_out(const int* __restrict__ ei,
                                             const float* __restrict__ ef,
                                             const float* __restrict__ Wm,
                                             float* __restrict__ out) {
    int gw = (blockIdx.x * blockDim.x + threadIdx.x) >> 5;
    int lane = threadIdx.x & 31;
    if (gw >= E_EDGES) return;
    int s = ei[gw];
    int d = ei[E_EDGES + gw];
    float x = ef[gw];

    float al = 0.f;
    if (lane < HEADS) {
        float sm = g_sum[d * HEADS + lane];
        al = __fdividef(g_attn[(size_t)gw * HEADS + lane], fmaxf(sm, 1e-12f));
    }

    const __half* Mrow = g_Mh + (size_t)s * MCOLS;
    const float* Wlast = Wm + (size_t)IN_F * MCOLS;
    float contrib = 0.f;
    #pragma unroll
    for (int hh = 0; hh < HEADS; hh++) {
        float a = __shfl_sync(0xffffffffu, al, hh);
        float mv = __half2float(Mrow[hh * OUT_F + lane]);
        contrib += a * (mv + x * __ldg(&Wlast[hh * OUT_F + lane]));
    }
    atomicAdd(&out[d * OUT_F + lane], contrib * 0.125f);   // fold mean over heads
}

// ---------------------------------------------------------------------------
extern "C" void kernel_launch(void* const* d_in, const int* in_sizes, int n_in,
                              void* d_out, int out_size) {
    const float* h   = (const float*)d_in[0];
    const int*   ei  = (const int*)d_in[1];
    const float* ef  = (const float*)d_in[2];
    const float* Wn  = (const float*)d_in[3];
    const float* We  = (const float*)d_in[4];
    const float* Asw = (const float*)d_in[5];
    const float* Adw = (const float*)d_in[6];
    const float* Wm  = (const float*)d_in[7];
    float* out = (float*)d_out;

    k_init<<<(N_NODES * OUT_F + 255) / 256, 256>>>(out);
    k_coef<<<1, 1024>>>(Wn, Asw, Adw);
    k_cvtW<<<(IN_F * MCOLS / 2 + 255) / 256, 256>>>(Wm);
    k_anode<<<N_NODES / 64, 256>>>(h);
    k_gemm<<<N_NODES / 64, 256>>>();
    k_score<<<(E_EDGES + 255) / 256, 256>>>(ei, ef, We);
    k_out<<<(E_EDGES * 32 + 511) / 512, 512>>>(ei, ef, Wm, out);
}

// round 13
// speedup vs baseline: 1.2925x; 1.0809x over previous
#include <cuda_runtime.h>
#include <cuda_fp16.h>
#include <mma.h>
#include <math.h>

using namespace nvcuda;

#define N_NODES 40000
#define E_EDGES 640000
#define IN_F 128
#define OUT_F 32
#define HEADS 8
#define MCOLS (HEADS * OUT_F)   // 256
#define NPAD 64                 // row padding for the S-GEMM tail block

// Scratch (static device globals; no allocation allowed).
__device__ __align__(16) __half g_Mh[N_NODES * MCOLS];           // h @ W_msg[:128] fp16
__device__ __align__(16) __half g_h16[(N_NODES + NPAD) * IN_F];  // h in fp16 (+pad rows)
__device__ __align__(16) __half g_W16[IN_F * MCOLS];             // W_msg[:128] fp16
__device__ __align__(32) __half g_C16[IN_F * 16];                // [csrc | cdst] fp16
__device__ __align__(16) float g_asrc[N_NODES * HEADS];
__device__ __align__(16) float g_adst[N_NODES * HEADS];
__device__ __align__(16) float g_sum[N_NODES * HEADS];   // softmax denominators
__device__ __align__(16) float g_attn[E_EDGES * HEADS];  // exp(score), edge order

// ---------------------------------------------------------------------------
__global__ void k_init(float* __restrict__ out) {
    int i = blockIdx.x * blockDim.x + threadIdx.x;
    if (i < N_NODES * OUT_F) out[i] = 0.f;
    if (i < N_NODES * HEADS) g_sum[i] = 0.f;
}

// ---------------------------------------------------------------------------
// fold W_node with attention vectors; emit fp16 coefficient matrix C16[128][16]:
// C16[i][h] = sum_f Wn[i,h*32+f]*att_s[h,f],  C16[i][8+h] = ... att_d ...
__global__ void k_coef(const float* __restrict__ Wn,
                       const float* __restrict__ att_s,
                       const float* __restrict__ att_d) {
    int t = threadIdx.x;             // 1024 threads: t = i*8 + h
    int i = t >> 3, hh = t & 7;
    float s1 = 0.f, s2 = 0.f;
    #pragma unroll
    for (int f = 0; f < OUT_F; f++) {
        float w = Wn[i * MCOLS + hh * OUT_F + f];
        s1 += w * att_s[hh * OUT_F + f];
        s2 += w * att_d[hh * OUT_F + f];
    }
    g_C16[i * 16 + hh]     = __float2half_rn(s1);
    g_C16[i * 16 + 8 + hh] = __float2half_rn(s2);
}

// ---------------------------------------------------------------------------
// convert W_msg[:128,:] to fp16 (32768 elems)
__global__ void k_cvtW(const float* __restrict__ Wm) {
    int i = blockIdx.x * blockDim.x + threadIdx.x;   // 0..16383, x2 floats
    float2 v = *(const float2*)(Wm + i * 2);
    *(__half2*)(g_W16 + i * 2) = __floats2half2_rn(v.x, v.y);
}

// ---------------------------------------------------------------------------
// convert h to fp16, streaming: thread handles 8 floats. 640000 threads.
__global__ void k_cvth(const float* __restrict__ h) {
    int i = blockIdx.x * blockDim.x + threadIdx.x;   // 0..639999
    const float* p = h + (size_t)i * 8;
    float4 a = *(const float4*)p;
    float4 b = *(const float4*)(p + 4);
    __half2 t[4];
    t[0] = __floats2half2_rn(a.x, a.y);
    t[1] = __floats2half2_rn(a.z, a.w);
    t[2] = __floats2half2_rn(b.x, b.y);
    t[3] = __floats2half2_rn(b.z, b.w);
    *(uint4*)(g_h16 + (size_t)i * 8) = *(uint4*)t;
}

// ---------------------------------------------------------------------------
// Attention pre-score GEMM: [asrc|adst] = h16 @ C16  (40000x128 @ 128x16).
// Warp per 16 rows, fragments straight from global (h16 L2-resident).
__global__ void __launch_bounds__(256) k_sgemm() {
    __shared__ __align__(16) float Cst[8][16][16];
    int wid = threadIdx.x >> 5, lane = threadIdx.x & 31;
    int row0 = blockIdx.x * 128 + wid * 16;

    wmma::fragment<wmma::accumulator, 16, 16, 16, float> c;
    wmma::fill_fragment(c, 0.f);
    #pragma unroll
    for (int k0 = 0; k0 < IN_F; k0 += 16) {
        wmma::fragment<wmma::matrix_a, 16, 16, 16, __half, wmma::row_major> a;
        wmma::fragment<wmma::matrix_b, 16, 16, 16, __half, wmma::row_major> b;
        wmma::load_matrix_sync(a, g_h16 + (size_t)row0 * IN_F + k0, IN_F);
        wmma::load_matrix_sync(b, g_C16 + k0 * 16, 16);
        wmma::mma_sync(c, a, b, c);
    }
    wmma::store_matrix_sync(&Cst[wid][0][0], c, 16, wmma::mem_row_major);
    __syncwarp();
    if (lane < 16) {
        int n = row0 + lane;
        if (n < N_NODES) {
            const float4* p = (const float4*)&Cst[wid][lane][0];
            *(float4*)&g_asrc[n * HEADS]     = p[0];
            *(float4*)&g_asrc[n * HEADS + 4] = p[1];
            *(float4*)&g_adst[n * HEADS]     = p[2];
            *(float4*)&g_adst[n * HEADS + 4] = p[3];
        }
    }
}

// ---------------------------------------------------------------------------
// Tensor-core GEMM: M = h16 @ W16, fp16 out (measured-best R12 version).
__global__ void __launch_bounds__(256) k_gemm() {
    __shared__ __align__(32) __half Ah[64][48];
    __shared__ __align__(32) __half Bh[32][272];
    __shared__ __align__(16) float Cst[8][16][16];
    int tid = threadIdx.x;
    int wid = tid >> 5, lane = tid & 31;
    int wm = wid >> 2;
    int wn = wid & 3;
    int m0 = blockIdx.x * 64;

    wmma::fragment<wmma::accumulator, 16, 16, 16, float> c[2][4];
    #pragma unroll
    for (int i = 0; i < 2; i++)
        #pragma unroll
        for (int j = 0; j < 4; j++) wmma::fill_fragment(c[i][j], 0.f);

    int ar = tid >> 2;               // 0..63
    int ac = (tid & 3) * 8;          // 0,8,16,24 (halves)
    int br = tid >> 3;               // 0..31
    int bc = (tid & 7) * 32;         // 0..224 (halves)

    for (int k0 = 0; k0 < IN_F; k0 += 32) {
        *(uint4*)&Ah[ar][ac] =
            *(const uint4*)(g_h16 + (size_t)(m0 + ar) * IN_F + k0 + ac);
        const __half* bg = g_W16 + (size_t)(k0 + br) * MCOLS + bc;
        #pragma unroll
        for (int q = 0; q < 4; q++)
            *(uint4*)&Bh[br][bc + q * 8] = *(const uint4*)(bg + q * 8);
        __syncthreads();
        #pragma unroll
        for (int kk = 0; kk < 32; kk += 16) {
            wmma::fragment<wmma::matrix_a, 16, 16, 16, __half, wmma::row_major> af[2];
            wmma::fragment<wmma::matrix_b, 16, 16, 16, __half, wmma::row_major> bf[4];
            #pragma unroll
            for (int i = 0; i < 2; i++)
                wmma::load_matrix_sync(af[i], &Ah[wm * 32 + i * 16][kk], 48);
            #pragma unroll
            for (int j = 0; j < 4; j++)
                wmma::load_matrix_sync(bf[j], &Bh[kk][wn * 64 + j * 16], 272);
            #pragma unroll
            for (int i = 0; i < 2; i++)
                #pragma unroll
                for (int j = 0; j < 4; j++)
                    wmma::mma_sync(c[i][j], af[i], bf[j], c[i][j]);
        }
        __syncthreads();
    }
    int rr = lane >> 1, cc = (lane & 1) * 8;
    #pragma unroll
    for (int i = 0; i < 2; i++)
        #pragma unroll
        for (int j = 0; j < 4; j++) {
            wmma::store_matrix_sync(&Cst[wid][0][0], c[i][j], 16, wmma::mem_row_major);
            __syncwarp();
            const float* sp = &Cst[wid][rr][cc];
            __half2 hv[4];
            #pragma unroll
            for (int q = 0; q < 4; q++)
                hv[q] = __floats2half2_rn(sp[q * 2], sp[q * 2 + 1]);
            int grow = m0 + wm * 32 + i * 16 + rr;
            int gcol = wn * 64 + j * 16 + cc;
            *(uint4*)(g_Mh + (size_t)grow * MCOLS + gcol) = *(uint4*)hv;
            __syncwarp();
        }
}

// ---------------------------------------------------------------------------
// edge pass: score -> leaky relu -> exp (no max shift; bounded scores),
// store p coalesced in edge order; denominator via two v4 vector reductions.
__global__ void k_score(const int* __restrict__ ei, const float* __restrict__ ef,
                        const float* __restrict__ We) {
    int e = blockIdx.x * blockDim.x + threadIdx.x;
    if (e >= E_EDGES) return;
    int s = ei[e];
    int d = ei[E_EDGES + e];
    float x = ef[e];

    float4 sa0 = *(const float4*)&g_asrc[s * HEADS];
    float4 sa1 = *(const float4*)&g_asrc[s * HEADS + 4];
    float4 da0 = *(const float4*)&g_adst[d * HEADS];
    float4 da1 = *(const float4*)&g_adst[d * HEADS + 4];
    float sv[8] = {sa0.x, sa0.y, sa0.z, sa0.w, sa1.x, sa1.y, sa1.z, sa1.w};
    float dv[8] = {da0.x, da0.y, da0.z, da0.w, da1.x, da1.y, da1.z, da1.w};

    float p[8];
    #pragma unroll
    for (int hh = 0; hh < HEADS; hh++) {
        float a = sv[hh] + dv[hh] + x * __ldg(&We[hh]);
        a = (a > 0.f) ? a : 0.2f * a;          // leaky relu
        p[hh] = __expf(a);
    }
    float* ap = &g_attn[(size_t)e * HEADS];
    *(float4*)ap       = make_float4(p[0], p[1], p[2], p[3]);
    *(float4*)(ap + 4) = make_float4(p[4], p[5], p[6], p[7]);

    float* sp = &g_sum[d * HEADS];             // 32B-aligned (d*8 floats)
    asm volatile("red.global.add.v4.f32 [%0], {%1, %2, %3, %4};"
                 :: "l"(sp), "f"(p[0]), "f"(p[1]), "f"(p[2]), "f"(p[3])
                 : "memory");
    asm volatile("red.global.add.v4.f32 [%0], {%1, %2, %3, %4};"
                 :: "l"(sp + 4), "f"(p[4]), "f"(p[5]), "f"(p[6]), "f"(p[7])
                 : "memory");
}

// ---------------------------------------------------------------------------
// final pass (measured-best): warp per edge, lane = output feature.
__global__ void __launch_bounds__(512) k_out(const int* __restrict__ ei,
                                             const float* __restrict__ ef,
                                             const float* __restrict__ Wm,
                                             float* __restrict__ out) {
    int gw = (blockIdx.x * blockDim.x + threadIdx.x) >> 5;
    int lane = threadIdx.x & 31;
    if (gw >= E_EDGES) return;
    int s = ei[gw];
    int d = ei[E_EDGES + gw];
    float x = ef[gw];

    float al = 0.f;
    if (lane < HEADS) {
        float sm = g_sum[d * HEADS + lane];
        al = __fdividef(g_attn[(size_t)gw * HEADS + lane], fmaxf(sm, 1e-12f));
    }

    const __half* Mrow = g_Mh + (size_t)s * MCOLS;
    const float* Wlast = Wm + (size_t)IN_F * MCOLS;
    float contrib = 0.f;
    #pragma unroll
    for (int hh = 0; hh < HEADS; hh++) {
        float a = __shfl_sync(0xffffffffu, al, hh);
        float mv = __half2float(Mrow[hh * OUT_F + lane]);
        contrib += a * (mv + x * __ldg(&Wlast[hh * OUT_F + lane]));
    }
    atomicAdd(&out[d * OUT_F + lane], contrib * 0.125f);   // fold mean over heads
}

// ---------------------------------------------------------------------------
extern "C" void kernel_launch(void* const* d_in, const int* in_sizes, int n_in,
                              void* d_out, int out_size) {
    const float* h   = (const float*)d_in[0];
    const int*   ei  = (const int*)d_in[1];
    const float* ef  = (const float*)d_in[2];
    const float* Wn  = (const float*)d_in[3];
    const float* We  = (const float*)d_in[4];
    const float* Asw = (const float*)d_in[5];
    const float* Adw = (const float*)d_in[6];
    const float* Wm  = (const float*)d_in[7];
    float* out = (float*)d_out;

    k_init<<<(N_NODES * OUT_F + 255) / 256, 256>>>(out);
    k_coef<<<1, 1024>>>(Wn, Asw, Adw);
    k_cvtW<<<(IN_F * MCOLS / 2 + 255) / 256, 256>>>(Wm);
    k_cvth<<<(N_NODES * IN_F / 8 + 255) / 256, 256>>>(h);
    k_sgemm<<<(N_NODES + 127) / 128, 256>>>();
    k_gemm<<<N_NODES / 64, 256>>>();
    k_score<<<(E_EDGES + 255) / 256, 256>>>(ei, ef, We);
    k_out<<<(E_EDGES * 32 + 511) / 512, 512>>>(ei, ef, Wm, out);
}

// round 14
// speedup vs baseline: 1.3225x; 1.0232x over previous
#include <cuda_runtime.h>
#include <cuda_fp16.h>
#include <mma.h>
#include <math.h>

using namespace nvcuda;

#define N_NODES 40000
#define E_EDGES 640000
#define IN_F 128
#define OUT_F 32
#define HEADS 8
#define MCOLS (HEADS * OUT_F)   // 256
#define NPAD 64                 // row padding for the S-GEMM tail block
#define GEMM_BLOCKS 625         // k_mid: blocks [0,625) = gemm, rest = score

// Scratch (static device globals; no allocation allowed).
__device__ __align__(16) __half g_Mh[N_NODES * MCOLS];           // h @ W_msg[:128] fp16
__device__ __align__(16) __half g_h16[(N_NODES + NPAD) * IN_F];  // h in fp16 (+pad rows)
__device__ __align__(16) __half g_W16[IN_F * MCOLS];             // W_msg[:128] fp16
__device__ __align__(32) __half g_C16[IN_F * 16];                // [csrc | cdst] fp16
__device__ __align__(16) float g_asrc[N_NODES * HEADS];
__device__ __align__(16) float g_adst[N_NODES * HEADS];
__device__ __align__(16) float g_sum[N_NODES * HEADS];   // softmax denominators
__device__ __align__(16) float g_attn[E_EDGES * HEADS];  // exp(score), edge order

// ---------------------------------------------------------------------------
__global__ void k_init(float* __restrict__ out) {
    int i = blockIdx.x * blockDim.x + threadIdx.x;
    if (i < N_NODES * OUT_F) out[i] = 0.f;
    if (i < N_NODES * HEADS) g_sum[i] = 0.f;
}

// ---------------------------------------------------------------------------
// fold W_node with attention vectors; emit fp16 coefficient matrix C16[128][16]
__global__ void k_coef(const float* __restrict__ Wn,
                       const float* __restrict__ att_s,
                       const float* __restrict__ att_d) {
    int t = threadIdx.x;             // 1024 threads: t = i*8 + h
    int i = t >> 3, hh = t & 7;
    float s1 = 0.f, s2 = 0.f;
    #pragma unroll
    for (int f = 0; f < OUT_F; f++) {
        float w = Wn[i * MCOLS + hh * OUT_F + f];
        s1 += w * att_s[hh * OUT_F + f];
        s2 += w * att_d[hh * OUT_F + f];
    }
    g_C16[i * 16 + hh]     = __float2half_rn(s1);
    g_C16[i * 16 + 8 + hh] = __float2half_rn(s2);
}

// ---------------------------------------------------------------------------
// convert W_msg[:128,:] to fp16 (32768 elems)
__global__ void k_cvtW(const float* __restrict__ Wm) {
    int i = blockIdx.x * blockDim.x + threadIdx.x;   // 0..16383, x2 floats
    float2 v = *(const float2*)(Wm + i * 2);
    *(__half2*)(g_W16 + i * 2) = __floats2half2_rn(v.x, v.y);
}

// ---------------------------------------------------------------------------
// convert h to fp16, streaming: thread handles 8 floats. 640000 threads.
__global__ void k_cvth(const float* __restrict__ h) {
    int i = blockIdx.x * blockDim.x + threadIdx.x;   // 0..639999
    const float* p = h + (size_t)i * 8;
    float4 a = *(const float4*)p;
    float4 b = *(const float4*)(p + 4);
    __half2 t[4];
    t[0] = __floats2half2_rn(a.x, a.y);
    t[1] = __floats2half2_rn(a.z, a.w);
    t[2] = __floats2half2_rn(b.x, b.y);
    t[3] = __floats2half2_rn(b.z, b.w);
    *(uint4*)(g_h16 + (size_t)i * 8) = *(uint4*)t;
}

// ---------------------------------------------------------------------------
// Attention pre-score GEMM: [asrc|adst] = h16 @ C16  (40000x128 @ 128x16).
__global__ void __launch_bounds__(256) k_sgemm() {
    __shared__ __align__(16) float Cst[8][16][16];
    int wid = threadIdx.x >> 5, lane = threadIdx.x & 31;
    int row0 = blockIdx.x * 128 + wid * 16;

    wmma::fragment<wmma::accumulator, 16, 16, 16, float> c;
    wmma::fill_fragment(c, 0.f);
    #pragma unroll
    for (int k0 = 0; k0 < IN_F; k0 += 16) {
        wmma::fragment<wmma::matrix_a, 16, 16, 16, __half, wmma::row_major> a;
        wmma::fragment<wmma::matrix_b, 16, 16, 16, __half, wmma::row_major> b;
        wmma::load_matrix_sync(a, g_h16 + (size_t)row0 * IN_F + k0, IN_F);
        wmma::load_matrix_sync(b, g_C16 + k0 * 16, 16);
        wmma::mma_sync(c, a, b, c);
    }
    wmma::store_matrix_sync(&Cst[wid][0][0], c, 16, wmma::mem_row_major);
    __syncwarp();
    if (lane < 16) {
        int n = row0 + lane;
        if (n < N_NODES) {
            const float4* p = (const float4*)&Cst[wid][lane][0];
            *(float4*)&g_asrc[n * HEADS]     = p[0];
            *(float4*)&g_asrc[n * HEADS + 4] = p[1];
            *(float4*)&g_adst[n * HEADS]     = p[2];
            *(float4*)&g_adst[n * HEADS + 4] = p[3];
        }
    }
}

// ---------------------------------------------------------------------------
// FUSED mid kernel: blocks [0,GEMM_BLOCKS) run the M-GEMM tile body (tensor/
// latency bound); remaining 2500 blocks run the edge score pass (L2/atomic
// bound). Independent data; co-resident blocks overlap complementary pipes.
__global__ void __launch_bounds__(256) k_mid(const int* __restrict__ ei,
                                             const float* __restrict__ ef,
                                             const float* __restrict__ We) {
    if (blockIdx.x < GEMM_BLOCKS) {
        // ---------------- GEMM body: M = h16 @ W16, fp16 out ----------------
        __shared__ __align__(32) __half Ah[64][48];
        __shared__ __align__(32) __half Bh[32][272];
        __shared__ __align__(16) float Cst[8][16][16];
        int tid = threadIdx.x;
        int wid = tid >> 5, lane = tid & 31;
        int wm = wid >> 2;
        int wn = wid & 3;
        int m0 = blockIdx.x * 64;

        wmma::fragment<wmma::accumulator, 16, 16, 16, float> c[2][4];
        #pragma unroll
        for (int i = 0; i < 2; i++)
            #pragma unroll
            for (int j = 0; j < 4; j++) wmma::fill_fragment(c[i][j], 0.f);

        int ar = tid >> 2;               // 0..63
        int ac = (tid & 3) * 8;          // 0,8,16,24 (halves)
        int br = tid >> 3;               // 0..31
        int bc = (tid & 7) * 32;         // 0..224 (halves)

        for (int k0 = 0; k0 < IN_F; k0 += 32) {
            *(uint4*)&Ah[ar][ac] =
                *(const uint4*)(g_h16 + (size_t)(m0 + ar) * IN_F + k0 + ac);
            const __half* bg = g_W16 + (size_t)(k0 + br) * MCOLS + bc;
            #pragma unroll
            for (int q = 0; q < 4; q++)
                *(uint4*)&Bh[br][bc + q * 8] = *(const uint4*)(bg + q * 8);
            __syncthreads();
            #pragma unroll
            for (int kk = 0; kk < 32; kk += 16) {
                wmma::fragment<wmma::matrix_a, 16, 16, 16, __half, wmma::row_major> af[2];
                wmma::fragment<wmma::matrix_b, 16, 16, 16, __half, wmma::row_major> bf[4];
                #pragma unroll
                for (int i = 0; i < 2; i++)
                    wmma::load_matrix_sync(af[i], &Ah[wm * 32 + i * 16][kk], 48);
                #pragma unroll
                for (int j = 0; j < 4; j++)
                    wmma::load_matrix_sync(bf[j], &Bh[kk][wn * 64 + j * 16], 272);
                #pragma unroll
                for (int i = 0; i < 2; i++)
                    #pragma unroll
                    for (int j = 0; j < 4; j++)
                        wmma::mma_sync(c[i][j], af[i], bf[j], c[i][j]);
            }
            __syncthreads();
        }
        int rr = lane >> 1, cc = (lane & 1) * 8;
        #pragma unroll
        for (int i = 0; i < 2; i++)
            #pragma unroll
            for (int j = 0; j < 4; j++) {
                wmma::store_matrix_sync(&Cst[wid][0][0], c[i][j], 16, wmma::mem_row_major);
                __syncwarp();
                const float* sp = &Cst[wid][rr][cc];
                __half2 hv[4];
                #pragma unroll
                for (int q = 0; q < 4; q++)
                    hv[q] = __floats2half2_rn(sp[q * 2], sp[q * 2 + 1]);
                int grow = m0 + wm * 32 + i * 16 + rr;
                int gcol = wn * 64 + j * 16 + cc;
                *(uint4*)(g_Mh + (size_t)grow * MCOLS + gcol) = *(uint4*)hv;
                __syncwarp();
            }
    } else {
        // ---------------- score body: exp(leaky(score)), denominators -------
        int e = (blockIdx.x - GEMM_BLOCKS) * 256 + threadIdx.x;
        if (e >= E_EDGES) return;
        int s = ei[e];
        int d = ei[E_EDGES + e];
        float x = ef[e];

        float4 sa0 = *(const float4*)&g_asrc[s * HEADS];
        float4 sa1 = *(const float4*)&g_asrc[s * HEADS + 4];
        float4 da0 = *(const float4*)&g_adst[d * HEADS];
        float4 da1 = *(const float4*)&g_adst[d * HEADS + 4];
        float sv[8] = {sa0.x, sa0.y, sa0.z, sa0.w, sa1.x, sa1.y, sa1.z, sa1.w};
        float dv[8] = {da0.x, da0.y, da0.z, da0.w, da1.x, da1.y, da1.z, da1.w};

        float p[8];
        #pragma unroll
        for (int hh = 0; hh < HEADS; hh++) {
            float a = sv[hh] + dv[hh] + x * __ldg(&We[hh]);
            a = (a > 0.f) ? a : 0.2f * a;          // leaky relu
            p[hh] = __expf(a);
        }
        float* ap = &g_attn[(size_t)e * HEADS];
        *(float4*)ap       = make_float4(p[0], p[1], p[2], p[3]);
        *(float4*)(ap + 4) = make_float4(p[4], p[5], p[6], p[7]);

        float* sp = &g_sum[d * HEADS];             // 32B-aligned (d*8 floats)
        asm volatile("red.global.add.v4.f32 [%0], {%1, %2, %3, %4};"
                     :: "l"(sp), "f"(p[0]), "f"(p[1]), "f"(p[2]), "f"(p[3])
                     : "memory");
        asm volatile("red.global.add.v4.f32 [%0], {%1, %2, %3, %4};"
                     :: "l"(sp + 4), "f"(p[4]), "f"(p[5]), "f"(p[6]), "f"(p[7])
                     : "memory");
    }
}

// ---------------------------------------------------------------------------
// final pass (measured-best): warp per edge, lane = output feature.
__global__ void __launch_bounds__(512) k_out(const int* __restrict__ ei,
                                             const float* __restrict__ ef,
                                             const float* __restrict__ Wm,
                                             float* __restrict__ out) {
    int gw = (blockIdx.x * blockDim.x + threadIdx.x) >> 5;
    int lane = threadIdx.x & 31;
    if (gw >= E_EDGES) return;
    int s = ei[gw];
    int d = ei[E_EDGES + gw];
    float x = ef[gw];

    float al = 0.f;
    if (lane < HEADS) {
        float sm = g_sum[d * HEADS + lane];
        al = __fdividef(g_attn[(size_t)gw * HEADS + lane], fmaxf(sm, 1e-12f));
    }

    const __half* Mrow = g_Mh + (size_t)s * MCOLS;
    const float* Wlast = Wm + (size_t)IN_F * MCOLS;
    float contrib = 0.f;
    #pragma unroll
    for (int hh = 0; hh < HEADS; hh++) {
        float a = __shfl_sync(0xffffffffu, al, hh);
        float mv = __half2float(Mrow[hh * OUT_F + lane]);
        contrib += a * (mv + x * __ldg(&Wlast[hh * OUT_F + lane]));
    }
    atomicAdd(&out[d * OUT_F + lane], contrib * 0.125f);   // fold mean over heads
}

// ---------------------------------------------------------------------------
extern "C" void kernel_launch(void* const* d_in, const int* in_sizes, int n_in,
                              void* d_out, int out_size) {
    const float* h   = (const float*)d_in[0];
    const int*   ei  = (const int*)d_in[1];
    const float* ef  = (const float*)d_in[2];
    const float* Wn  = (const float*)d_in[3];
    const float* We  = (const float*)d_in[4];
    const float* Asw = (const float*)d_in[5];
    const float* Adw = (const float*)d_in[6];
    const float* Wm  = (const float*)d_in[7];
    float* out = (float*)d_out;

    k_init<<<(N_NODES * OUT_F + 255) / 256, 256>>>(out);
    k_coef<<<1, 1024>>>(Wn, Asw, Adw);
    k_cvtW<<<(IN_F * MCOLS / 2 + 255) / 256, 256>>>(Wm);
    k_cvth<<<(N_NODES * IN_F / 8 + 255) / 256, 256>>>(h);
    k_sgemm<<<(N_NODES + 127) / 128, 256>>>();
    k_mid<<<GEMM_BLOCKS + (E_EDGES + 255) / 256, 256>>>(ei, ef, We);
    k_out<<<(E_EDGES * 32 + 511) / 512, 512>>>(ei, ef, Wm, out);
}

// round 15
// speedup vs baseline: 1.6347x; 1.2361x over previous
#include <cuda_runtime.h>
#include <cuda_fp16.h>
#include <mma.h>
#include <math.h>

using namespace nvcuda;

#define N_NODES 40000
#define E_EDGES 640000
#define IN_F 128
#define OUT_F 32
#define HEADS 8
#define MCOLS (HEADS * OUT_F)   // 256
#define NPAD 64                 // row padding for the S-GEMM tail block
#define GEMM_BLOCKS 625         // k_mid: blocks [0,625) = gemm, rest = score

// Scratch (static device globals; no allocation allowed).
__device__ __align__(16) __half g_Mh[N_NODES * MCOLS];           // h @ W_msg[:128] fp16
__device__ __align__(16) __half g_h16[(N_NODES + NPAD) * IN_F];  // h in fp16 (+pad rows)
__device__ __align__(16) __half g_W16[IN_F * MCOLS];             // W_msg[:128] fp16
__device__ __align__(32) __half g_C16[IN_F * 16];                // [csrc | cdst] fp16
__device__ __align__(16) float g_asrc[N_NODES * HEADS];
__device__ __align__(16) float g_adst[N_NODES * HEADS];
__device__ __align__(16) float g_sum[N_NODES * HEADS];   // softmax denominators
__device__ __align__(16) float g_attn[E_EDGES * HEADS];  // exp(score), edge order

// ---------------------------------------------------------------------------
__global__ void k_init(float* __restrict__ out) {
    int i = blockIdx.x * blockDim.x + threadIdx.x;
    if (i < N_NODES * OUT_F) out[i] = 0.f;
    if (i < N_NODES * HEADS) g_sum[i] = 0.f;
}

// ---------------------------------------------------------------------------
// fold W_node with attention vectors; emit fp16 coefficient matrix C16[128][16]
__global__ void k_coef(const float* __restrict__ Wn,
                       const float* __restrict__ att_s,
                       const float* __restrict__ att_d) {
    int t = threadIdx.x;             // 1024 threads: t = i*8 + h
    int i = t >> 3, hh = t & 7;
    float s1 = 0.f, s2 = 0.f;
    #pragma unroll
    for (int f = 0; f < OUT_F; f++) {
        float w = Wn[i * MCOLS + hh * OUT_F + f];
        s1 += w * att_s[hh * OUT_F + f];
        s2 += w * att_d[hh * OUT_F + f];
    }
    g_C16[i * 16 + hh]     = __float2half_rn(s1);
    g_C16[i * 16 + 8 + hh] = __float2half_rn(s2);
}

// ---------------------------------------------------------------------------
// convert W_msg[:128,:] to fp16 (32768 elems)
__global__ void k_cvtW(const float* __restrict__ Wm) {
    int i = blockIdx.x * blockDim.x + threadIdx.x;   // 0..16383, x2 floats
    float2 v = *(const float2*)(Wm + i * 2);
    *(__half2*)(g_W16 + i * 2) = __floats2half2_rn(v.x, v.y);
}

// ---------------------------------------------------------------------------
// convert h to fp16, streaming: thread handles 8 floats. 640000 threads.
__global__ void k_cvth(const float* __restrict__ h) {
    int i = blockIdx.x * blockDim.x + threadIdx.x;   // 0..639999
    const float* p = h + (size_t)i * 8;
    float4 a = *(const float4*)p;
    float4 b = *(const float4*)(p + 4);
    __half2 t[4];
    t[0] = __floats2half2_rn(a.x, a.y);
    t[1] = __floats2half2_rn(a.z, a.w);
    t[2] = __floats2half2_rn(b.x, b.y);
    t[3] = __floats2half2_rn(b.z, b.w);
    *(uint4*)(g_h16 + (size_t)i * 8) = *(uint4*)t;
}

// ---------------------------------------------------------------------------
// Attention pre-score GEMM: [asrc|adst] = h16 @ C16  (40000x128 @ 128x16).
__global__ void __launch_bounds__(256) k_sgemm() {
    __shared__ __align__(16) float Cst[8][16][16];
    int wid = threadIdx.x >> 5, lane = threadIdx.x & 31;
    int row0 = blockIdx.x * 128 + wid * 16;

    wmma::fragment<wmma::accumulator, 16, 16, 16, float> c;
    wmma::fill_fragment(c, 0.f);
    #pragma unroll
    for (int k0 = 0; k0 < IN_F; k0 += 16) {
        wmma::fragment<wmma::matrix_a, 16, 16, 16, __half, wmma::row_major> a;
        wmma::fragment<wmma::matrix_b, 16, 16, 16, __half, wmma::row_major> b;
        wmma::load_matrix_sync(a, g_h16 + (size_t)row0 * IN_F + k0, IN_F);
        wmma::load_matrix_sync(b, g_C16 + k0 * 16, 16);
        wmma::mma_sync(c, a, b, c);
    }
    wmma::store_matrix_sync(&Cst[wid][0][0], c, 16, wmma::mem_row_major);
    __syncwarp();
    if (lane < 16) {
        int n = row0 + lane;
        if (n < N_NODES) {
            const float4* p = (const float4*)&Cst[wid][lane][0];
            *(float4*)&g_asrc[n * HEADS]     = p[0];
            *(float4*)&g_asrc[n * HEADS + 4] = p[1];
            *(float4*)&g_adst[n * HEADS]     = p[2];
            *(float4*)&g_adst[n * HEADS + 4] = p[3];
        }
    }
}

// ---------------------------------------------------------------------------
// FUSED mid kernel: blocks [0,GEMM_BLOCKS) run the M-GEMM tile body; the
// remaining 2500 blocks run the edge score pass. (Measured win in R14.)
__global__ void __launch_bounds__(256) k_mid(const int* __restrict__ ei,
                                             const float* __restrict__ ef,
                                             const float* __restrict__ We) {
    if (blockIdx.x < GEMM_BLOCKS) {
        __shared__ __align__(32) __half Ah[64][48];
        __shared__ __align__(32) __half Bh[32][272];
        __shared__ __align__(16) float Cst[8][16][16];
        int tid = threadIdx.x;
        int wid = tid >> 5, lane = tid & 31;
        int wm = wid >> 2;
        int wn = wid & 3;
        int m0 = blockIdx.x * 64;

        wmma::fragment<wmma::accumulator, 16, 16, 16, float> c[2][4];
        #pragma unroll
        for (int i = 0; i < 2; i++)
            #pragma unroll
            for (int j = 0; j < 4; j++) wmma::fill_fragment(c[i][j], 0.f);

        int ar = tid >> 2;               // 0..63
        int ac = (tid & 3) * 8;          // 0,8,16,24 (halves)
        int br = tid >> 3;               // 0..31
        int bc = (tid & 7) * 32;         // 0..224 (halves)

        for (int k0 = 0; k0 < IN_F; k0 += 32) {
            *(uint4*)&Ah[ar][ac] =
                *(const uint4*)(g_h16 + (size_t)(m0 + ar) * IN_F + k0 + ac);
            const __half* bg = g_W16 + (size_t)(k0 + br) * MCOLS + bc;
            #pragma unroll
            for (int q = 0; q < 4; q++)
                *(uint4*)&Bh[br][bc + q * 8] = *(const uint4*)(bg + q * 8);
            __syncthreads();
            #pragma unroll
            for (int kk = 0; kk < 32; kk += 16) {
                wmma::fragment<wmma::matrix_a, 16, 16, 16, __half, wmma::row_major> af[2];
                wmma::fragment<wmma::matrix_b, 16, 16, 16, __half, wmma::row_major> bf[4];
                #pragma unroll
                for (int i = 0; i < 2; i++)
                    wmma::load_matrix_sync(af[i], &Ah[wm * 32 + i * 16][kk], 48);
                #pragma unroll
                for (int j = 0; j < 4; j++)
                    wmma::load_matrix_sync(bf[j], &Bh[kk][wn * 64 + j * 16], 272);
                #pragma unroll
                for (int i = 0; i < 2; i++)
                    #pragma unroll
                    for (int j = 0; j < 4; j++)
                        wmma::mma_sync(c[i][j], af[i], bf[j], c[i][j]);
            }
            __syncthreads();
        }
        int rr = lane >> 1, cc = (lane & 1) * 8;
        #pragma unroll
        for (int i = 0; i < 2; i++)
            #pragma unroll
            for (int j = 0; j < 4; j++) {
                wmma::store_matrix_sync(&Cst[wid][0][0], c[i][j], 16, wmma::mem_row_major);
                __syncwarp();
                const float* sp = &Cst[wid][rr][cc];
                __half2 hv[4];
                #pragma unroll
                for (int q = 0; q < 4; q++)
                    hv[q] = __floats2half2_rn(sp[q * 2], sp[q * 2 + 1]);
                int grow = m0 + wm * 32 + i * 16 + rr;
                int gcol = wn * 64 + j * 16 + cc;
                *(uint4*)(g_Mh + (size_t)grow * MCOLS + gcol) = *(uint4*)hv;
                __syncwarp();
            }
    } else {
        int e = (blockIdx.x - GEMM_BLOCKS) * 256 + threadIdx.x;
        if (e >= E_EDGES) return;
        int s = ei[e];
        int d = ei[E_EDGES + e];
        float x = ef[e];

        float4 sa0 = *(const float4*)&g_asrc[s * HEADS];
        float4 sa1 = *(const float4*)&g_asrc[s * HEADS + 4];
        float4 da0 = *(const float4*)&g_adst[d * HEADS];
        float4 da1 = *(const float4*)&g_adst[d * HEADS + 4];
        float sv[8] = {sa0.x, sa0.y, sa0.z, sa0.w, sa1.x, sa1.y, sa1.z, sa1.w};
        float dv[8] = {da0.x, da0.y, da0.z, da0.w, da1.x, da1.y, da1.z, da1.w};

        float p[8];
        #pragma unroll
        for (int hh = 0; hh < HEADS; hh++) {
            float a = sv[hh] + dv[hh] + x * __ldg(&We[hh]);
            a = (a > 0.f) ? a : 0.2f * a;          // leaky relu
            p[hh] = __expf(a);
        }
        float* ap = &g_attn[(size_t)e * HEADS];
        *(float4*)ap       = make_float4(p[0], p[1], p[2], p[3]);
        *(float4*)(ap + 4) = make_float4(p[4], p[5], p[6], p[7]);

        float* sp = &g_sum[d * HEADS];             // 32B-aligned (d*8 floats)
        asm volatile("red.global.add.v4.f32 [%0], {%1, %2, %3, %4};"
                     :: "l"(sp), "f"(p[0]), "f"(p[1]), "f"(p[2]), "f"(p[3])
                     : "memory");
        asm volatile("red.global.add.v4.f32 [%0], {%1, %2, %3, %4};"
                     :: "l"(sp + 4), "f"(p[4]), "f"(p[5]), "f"(p[6]), "f"(p[7])
                     : "memory");
    }
}

// ---------------------------------------------------------------------------
// final pass v2: 8 lanes per edge (4 edges/warp), grid-stride loop.
// Lane i owns features i*4..i*4+3 across all 8 heads: 8x LDG.64 for M,
// W cached in registers across iterations, one red.v4 per lane (8/edge).
__global__ void __launch_bounds__(256) k_out(const int* __restrict__ ei,
                                             const float* __restrict__ ef,
                                             const float* __restrict__ Wm,
                                             float* __restrict__ out) {
    int lane = threadIdx.x & 31;
    int g = lane >> 3;               // edge slot within warp (0..3)
    int i = lane & 7;                // feature cluster (4 feats)
    // cache W_msg edge-feat row for this cluster: wreg[h] = W[128, h*32+i*4 ..+3]
    float4 wreg[HEADS];
    const float* Wl = Wm + (size_t)IN_F * MCOLS + i * 4;
    #pragma unroll
    for (int hh = 0; hh < HEADS; hh++)
        wreg[hh] = __ldg((const float4*)(Wl + hh * OUT_F));

    int warpId = (blockIdx.x * blockDim.x + threadIdx.x) >> 5;
    int nWarps = (gridDim.x * blockDim.x) >> 5;
    unsigned gmask = 0xFFu << (g * 8);

    for (int e4 = warpId; e4 < E_EDGES / 4; e4 += nWarps) {
        int e = e4 * 4 + g;
        int s = ei[e];
        int d = ei[E_EDGES + e];
        float x = ef[e];

        // lane computes alpha for head i of its edge; broadcast via shfl
        float sm = g_sum[d * HEADS + i];
        float al = __fdividef(g_attn[(size_t)e * HEADS + i], fmaxf(sm, 1e-12f));

        // M rows for this edge, cluster i: 8 heads x 4 fp16 (LDG.64 each)
        float acc[4] = {0.f, 0.f, 0.f, 0.f};
        const __half* Mrow = g_Mh + (size_t)s * MCOLS + i * 4;
        #pragma unroll
        for (int hh = 0; hh < HEADS; hh++) {
            float a = __shfl_sync(0xffffffffu, al, g * 8 + hh);
            uint2 mv = *(const uint2*)(Mrow + hh * OUT_F);
            float2 m0 = __half22float2(*(__half2*)&mv.x);
            float2 m1 = __half22float2(*(__half2*)&mv.y);
            acc[0] = fmaf(a, fmaf(x, wreg[hh].x, m0.x), acc[0]);
            acc[1] = fmaf(a, fmaf(x, wreg[hh].y, m0.y), acc[1]);
            acc[2] = fmaf(a, fmaf(x, wreg[hh].z, m1.x), acc[2]);
            acc[3] = fmaf(a, fmaf(x, wreg[hh].w, m1.y), acc[3]);
        }
        float* op = out + (size_t)d * OUT_F + i * 4;   // 16B aligned
        asm volatile("red.global.add.v4.f32 [%0], {%1, %2, %3, %4};"
                     :: "l"(op), "f"(acc[0] * 0.125f), "f"(acc[1] * 0.125f),
                        "f"(acc[2] * 0.125f), "f"(acc[3] * 0.125f) : "memory");
    }
}

// ---------------------------------------------------------------------------
extern "C" void kernel_launch(void* const* d_in, const int* in_sizes, int n_in,
                              void* d_out, int out_size) {
    const float* h   = (const float*)d_in[0];
    const int*   ei  = (const int*)d_in[1];
    const float* ef  = (const float*)d_in[2];
    const float* Wn  = (const float*)d_in[3];
    const float* We  = (const float*)d_in[4];
    const float* Asw = (const float*)d_in[5];
    const float* Adw = (const float*)d_in[6];
    const float* Wm  = (const float*)d_in[7];
    float* out = (float*)d_out;

    k_init<<<(N_NODES * OUT_F + 255) / 256, 256>>>(out);
    k_coef<<<1, 1024>>>(Wn, Asw, Adw);
    k_cvtW<<<(IN_F * MCOLS / 2 + 255) / 256, 256>>>(Wm);
    k_cvth<<<(N_NODES * IN_F / 8 + 255) / 256, 256>>>(h);
    k_sgemm<<<(N_NODES + 127) / 128, 256>>>();
    k_mid<<<GEMM_BLOCKS + (E_EDGES + 255) / 256, 256>>>(ei, ef, We);
    k_out<<<2960, 256>>>(ei, ef, Wm, out);
}

// round 16
// speedup vs baseline: 2.0074x; 1.2280x over previous
#include <cuda_runtime.h>
#include <cuda_fp16.h>
#include <mma.h>
#include <math.h>

using namespace nvcuda;

#define N_NODES 40000
#define E_EDGES 640000
#define IN_F 128
#define OUT_F 32
#define HEADS 8
#define MCOLS (HEADS * OUT_F)   // 256
#define NPAD 128                // row padding (sgemm tail block)
#define GEMM_BLOCKS 625         // k_mid: blocks [0,625) = gemm, rest = score

// prep-kernel block partition
#define PREP_INIT_BLOCKS 5000   // 5000*256 = 1.28M >= N*32, N*8
#define PREP_CVTW_BLOCKS 64     // 64*256*2 floats = 32768
#define PREP_COEF_BLOCKS 4      // 4*256 = 1024 (i,h) pairs

// Scratch (static device globals; no allocation allowed).
__device__ __align__(16) __half g_Mh[N_NODES * MCOLS];           // h @ W_msg[:128] fp16
__device__ __align__(16) __half g_h16[(N_NODES + NPAD) * IN_F];  // h in fp16
__device__ __align__(16) __half g_W16[IN_F * MCOLS];             // W_msg[:128] fp16
__device__ __align__(32) __half g_C16[IN_F * 16];                // [csrc | cdst] fp16
__device__ __align__(16) float g_asrc[N_NODES * HEADS];
__device__ __align__(16) float g_adst[N_NODES * HEADS];
__device__ __align__(16) float g_sum[N_NODES * HEADS];   // softmax denominators
__device__ __align__(16) float g_attn[E_EDGES * HEADS];  // exp(score), edge order

// ---------------------------------------------------------------------------
// fused prep: [0,5000) zero out+g_sum; [5000,5064) cvt W_msg; [5064,5068) coef
__global__ void __launch_bounds__(256) k_prep(float* __restrict__ out,
                                              const float* __restrict__ Wm,
                                              const float* __restrict__ Wn,
                                              const float* __restrict__ att_s,
                                              const float* __restrict__ att_d) {
    int b = blockIdx.x;
    if (b < PREP_INIT_BLOCKS) {
        int i = b * 256 + threadIdx.x;
        if (i < N_NODES * OUT_F) out[i] = 0.f;
        if (i < N_NODES * HEADS) g_sum[i] = 0.f;
    } else if (b < PREP_INIT_BLOCKS + PREP_CVTW_BLOCKS) {
        int i = (b - PREP_INIT_BLOCKS) * 256 + threadIdx.x;   // 0..16383
        float2 v = *(const float2*)(Wm + i * 2);
        *(__half2*)(g_W16 + i * 2) = __floats2half2_rn(v.x, v.y);
    } else {
        int t = (b - PREP_INIT_BLOCKS - PREP_CVTW_BLOCKS) * 256 + threadIdx.x;
        int i = t >> 3, hh = t & 7;
        float s1 = 0.f, s2 = 0.f;
        #pragma unroll
        for (int f = 0; f < OUT_F; f++) {
            float w = Wn[i * MCOLS + hh * OUT_F + f];
            s1 += w * att_s[hh * OUT_F + f];
            s2 += w * att_d[hh * OUT_F + f];
        }
        g_C16[i * 16 + hh]     = __float2half_rn(s1);
        g_C16[i * 16 + 8 + hh] = __float2half_rn(s2);
    }
}

// ---------------------------------------------------------------------------
// fused h-convert + pre-score GEMM. Block = 128 rows: convert fp32->fp16 into
// smem AND g_h16, then [asrc|adst] = Hs @ C16 via wmma.
__global__ void __launch_bounds__(256) k_sgemm(const float* __restrict__ h) {
    __shared__ __align__(16) __half Hs[128][128];     // 32 KB
    __shared__ __align__(16) float Cst[8][16][16];
    int tid = threadIdx.x;
    int n0 = blockIdx.x * 128;
    #pragma unroll
    for (int q = 0; q < 8; q++) {
        int idx = q * 2048 + tid * 8;     // flat elem idx, 8 floats per thread
        int r = idx >> 7, c = idx & 127;
        int grow = n0 + r;
        __half2 t16[4];
        if (grow < N_NODES) {
            const float* p = h + (size_t)grow * IN_F + c;
            float4 a = *(const float4*)p;
            float4 bb = *(const float4*)(p + 4);
            t16[0] = __floats2half2_rn(a.x, a.y);
            t16[1] = __floats2half2_rn(a.z, a.w);
            t16[2] = __floats2half2_rn(bb.x, bb.y);
            t16[3] = __floats2half2_rn(bb.z, bb.w);
            *(uint4*)(g_h16 + (size_t)grow * IN_F + c) = *(uint4*)t16;
        } else {
            t16[0] = t16[1] = t16[2] = t16[3] = __half2half2(__float2half(0.f));
        }
        *(uint4*)&Hs[r][c] = *(uint4*)t16;
    }
    __syncthreads();
    int wid = tid >> 5, lane = tid & 31;
    int row0 = wid * 16;
    wmma::fragment<wmma::accumulator, 16, 16, 16, float> c;
    wmma::fill_fragment(c, 0.f);
    #pragma unroll
    for (int k0 = 0; k0 < IN_F; k0 += 16) {
        wmma::fragment<wmma::matrix_a, 16, 16, 16, __half, wmma::row_major> a;
        wmma::fragment<wmma::matrix_b, 16, 16, 16, __half, wmma::row_major> b;
        wmma::load_matrix_sync(a, &Hs[row0][k0], 128);
        wmma::load_matrix_sync(b, g_C16 + k0 * 16, 16);
        wmma::mma_sync(c, a, b, c);
    }
    wmma::store_matrix_sync(&Cst[wid][0][0], c, 16, wmma::mem_row_major);
    __syncwarp();
    if (lane < 16) {
        int n = n0 + row0 + lane;
        if (n < N_NODES) {
            const float4* p = (const float4*)&Cst[wid][lane][0];
            *(float4*)&g_asrc[n * HEADS]     = p[0];
            *(float4*)&g_asrc[n * HEADS + 4] = p[1];
            *(float4*)&g_adst[n * HEADS]     = p[2];
            *(float4*)&g_adst[n * HEADS + 4] = p[3];
        }
    }
}

// ---------------------------------------------------------------------------
// FUSED mid kernel: blocks [0,GEMM_BLOCKS) run the M-GEMM; remaining 1250
// blocks run the score pass with 2 edges/thread (e and e+E/2) for MLP.
__global__ void __launch_bounds__(256) k_mid(const int* __restrict__ ei,
                                             const float* __restrict__ ef,
                                             const float* __restrict__ We) {
    if (blockIdx.x < GEMM_BLOCKS) {
        __shared__ __align__(32) __half Ah[64][48];
        __shared__ __align__(32) __half Bh[32][272];
        __shared__ __align__(16) float Cst[8][16][16];
        int tid = threadIdx.x;
        int wid = tid >> 5, lane = tid & 31;
        int wm = wid >> 2;
        int wn = wid & 3;
        int m0 = blockIdx.x * 64;

        wmma::fragment<wmma::accumulator, 16, 16, 16, float> c[2][4];
        #pragma unroll
        for (int i = 0; i < 2; i++)
            #pragma unroll
            for (int j = 0; j < 4; j++) wmma::fill_fragment(c[i][j], 0.f);

        int ar = tid >> 2;               // 0..63
        int ac = (tid & 3) * 8;          // halves
        int br = tid >> 3;               // 0..31
        int bc = (tid & 7) * 32;         // halves

        for (int k0 = 0; k0 < IN_F; k0 += 32) {
            *(uint4*)&Ah[ar][ac] =
                *(const uint4*)(g_h16 + (size_t)(m0 + ar) * IN_F + k0 + ac);
            const __half* bg = g_W16 + (size_t)(k0 + br) * MCOLS + bc;
            #pragma unroll
            for (int q = 0; q < 4; q++)
                *(uint4*)&Bh[br][bc + q * 8] = *(const uint4*)(bg + q * 8);
            __syncthreads();
            #pragma unroll
            for (int kk = 0; kk < 32; kk += 16) {
                wmma::fragment<wmma::matrix_a, 16, 16, 16, __half, wmma::row_major> af[2];
                wmma::fragment<wmma::matrix_b, 16, 16, 16, __half, wmma::row_major> bf[4];
                #pragma unroll
                for (int i = 0; i < 2; i++)
                    wmma::load_matrix_sync(af[i], &Ah[wm * 32 + i * 16][kk], 48);
                #pragma unroll
                for (int j = 0; j < 4; j++)
                    wmma::load_matrix_sync(bf[j], &Bh[kk][wn * 64 + j * 16], 272);
                #pragma unroll
                for (int i = 0; i < 2; i++)
                    #pragma unroll
                    for (int j = 0; j < 4; j++)
                        wmma::mma_sync(c[i][j], af[i], bf[j], c[i][j]);
            }
            __syncthreads();
        }
        int rr = lane >> 1, cc = (lane & 1) * 8;
        #pragma unroll
        for (int i = 0; i < 2; i++)
            #pragma unroll
            for (int j = 0; j < 4; j++) {
                wmma::store_matrix_sync(&Cst[wid][0][0], c[i][j], 16, wmma::mem_row_major);
                __syncwarp();
                const float* sp = &Cst[wid][rr][cc];
                __half2 hv[4];
                #pragma unroll
                for (int q = 0; q < 4; q++)
                    hv[q] = __floats2half2_rn(sp[q * 2], sp[q * 2 + 1]);
                int grow = m0 + wm * 32 + i * 16 + rr;
                int gcol = wn * 64 + j * 16 + cc;
                *(uint4*)(g_Mh + (size_t)grow * MCOLS + gcol) = *(uint4*)hv;
                __syncwarp();
            }
    } else {
        // score: 2 independent edges per thread for MLP
        int base = (blockIdx.x - GEMM_BLOCKS) * 256 + threadIdx.x;
        int ee[2] = {base, base + E_EDGES / 2};
        int s[2], d[2];
        float x[2];
        #pragma unroll
        for (int u = 0; u < 2; u++) {
            s[u] = ei[ee[u]];
            d[u] = ei[E_EDGES + ee[u]];
            x[u] = ef[ee[u]];
        }
        float4 sa0[2], sa1[2], da0[2], da1[2];
        #pragma unroll
        for (int u = 0; u < 2; u++) {
            sa0[u] = *(const float4*)&g_asrc[s[u] * HEADS];
            sa1[u] = *(const float4*)&g_asrc[s[u] * HEADS + 4];
            da0[u] = *(const float4*)&g_adst[d[u] * HEADS];
            da1[u] = *(const float4*)&g_adst[d[u] * HEADS + 4];
        }
        #pragma unroll
        for (int u = 0; u < 2; u++) {
            float sv[8] = {sa0[u].x, sa0[u].y, sa0[u].z, sa0[u].w,
                           sa1[u].x, sa1[u].y, sa1[u].z, sa1[u].w};
            float dv[8] = {da0[u].x, da0[u].y, da0[u].z, da0[u].w,
                           da1[u].x, da1[u].y, da1[u].z, da1[u].w};
            float p[8];
            #pragma unroll
            for (int hh = 0; hh < HEADS; hh++) {
                float a = sv[hh] + dv[hh] + x[u] * __ldg(&We[hh]);
                a = (a > 0.f) ? a : 0.2f * a;          // leaky relu
                p[hh] = __expf(a);
            }
            float* ap = &g_attn[(size_t)ee[u] * HEADS];
            *(float4*)ap       = make_float4(p[0], p[1], p[2], p[3]);
            *(float4*)(ap + 4) = make_float4(p[4], p[5], p[6], p[7]);
            float* sp = &g_sum[d[u] * HEADS];
            asm volatile("red.global.add.v4.f32 [%0], {%1, %2, %3, %4};"
                         :: "l"(sp), "f"(p[0]), "f"(p[1]), "f"(p[2]), "f"(p[3])
                         : "memory");
            asm volatile("red.global.add.v4.f32 [%0], {%1, %2, %3, %4};"
                         :: "l"(sp + 4), "f"(p[4]), "f"(p[5]), "f"(p[6]), "f"(p[7])
                         : "memory");
        }
    }
}

// ---------------------------------------------------------------------------
// final pass v3: 8 lanes per edge, 2 edges per group-iteration (MLP x2).
// Lane i owns features i*4..i*4+3 across all 8 heads.
__global__ void __launch_bounds__(256) k_out(const int* __restrict__ ei,
                                             const float* __restrict__ ef,
                                             const float* __restrict__ Wm,
                                             float* __restrict__ out) {
    int lane = threadIdx.x & 31;
    int g = lane >> 3;               // edge slot within warp (0..3)
    int i = lane & 7;                // feature cluster (4 feats)
    float4 wreg[HEADS];
    const float* Wl = Wm + (size_t)IN_F * MCOLS + i * 4;
    #pragma unroll
    for (int hh = 0; hh < HEADS; hh++)
        wreg[hh] = __ldg((const float4*)(Wl + hh * OUT_F));

    int warpId = (blockIdx.x * blockDim.x + threadIdx.x) >> 5;
    int nWarps = (gridDim.x * blockDim.x) >> 5;

    for (int e8 = warpId; e8 < E_EDGES / 8; e8 += nWarps) {
        int e0 = e8 * 8 + g;
        int e1 = e0 + 4;
        int s0 = ei[e0], d0 = ei[E_EDGES + e0];
        int s1 = ei[e1], d1 = ei[E_EDGES + e1];
        float x0 = ef[e0], x1 = ef[e1];

        float sm0 = g_sum[d0 * HEADS + i];
        float sm1 = g_sum[d1 * HEADS + i];
        float at0 = g_attn[(size_t)e0 * HEADS + i];
        float at1 = g_attn[(size_t)e1 * HEADS + i];
        float al0 = __fdividef(at0, fmaxf(sm0, 1e-12f));
        float al1 = __fdividef(at1, fmaxf(sm1, 1e-12f));

        const __half* M0 = g_Mh + (size_t)s0 * MCOLS + i * 4;
        const __half* M1 = g_Mh + (size_t)s1 * MCOLS + i * 4;
        float acc0[4] = {0.f, 0.f, 0.f, 0.f};
        float acc1[4] = {0.f, 0.f, 0.f, 0.f};
        #pragma unroll
        for (int hh = 0; hh < HEADS; hh++) {
            float a0 = __shfl_sync(0xffffffffu, al0, g * 8 + hh);
            float a1 = __shfl_sync(0xffffffffu, al1, g * 8 + hh);
            uint2 mv0 = *(const uint2*)(M0 + hh * OUT_F);
            uint2 mv1 = *(const uint2*)(M1 + hh * OUT_F);
            float2 p00 = __half22float2(*(__half2*)&mv0.x);
            float2 p01 = __half22float2(*(__half2*)&mv0.y);
            float2 p10 = __half22float2(*(__half2*)&mv1.x);
            float2 p11 = __half22float2(*(__half2*)&mv1.y);
            acc0[0] = fmaf(a0, fmaf(x0, wreg[hh].x, p00.x), acc0[0]);
            acc0[1] = fmaf(a0, fmaf(x0, wreg[hh].y, p00.y), acc0[1]);
            acc0[2] = fmaf(a0, fmaf(x0, wreg[hh].z, p01.x), acc0[2]);
            acc0[3] = fmaf(a0, fmaf(x0, wreg[hh].w, p01.y), acc0[3]);
            acc1[0] = fmaf(a1, fmaf(x1, wreg[hh].x, p10.x), acc1[0]);
            acc1[1] = fmaf(a1, fmaf(x1, wreg[hh].y, p10.y), acc1[1]);
            acc1[2] = fmaf(a1, fmaf(x1, wreg[hh].z, p11.x), acc1[2]);
            acc1[3] = fmaf(a1, fmaf(x1, wreg[hh].w, p11.y), acc1[3]);
        }
        float* op0 = out + (size_t)d0 * OUT_F + i * 4;
        float* op1 = out + (size_t)d1 * OUT_F + i * 4;
        asm volatile("red.global.add.v4.f32 [%0], {%1, %2, %3, %4};"
                     :: "l"(op0), "f"(acc0[0] * 0.125f), "f"(acc0[1] * 0.125f),
                        "f"(acc0[2] * 0.125f), "f"(acc0[3] * 0.125f) : "memory");
        asm volatile("red.global.add.v4.f32 [%0], {%1, %2, %3, %4};"
                     :: "l"(op1), "f"(acc1[0] * 0.125f), "f"(acc1[1] * 0.125f),
                        "f"(acc1[2] * 0.125f), "f"(acc1[3] * 0.125f) : "memory");
    }
}

// ---------------------------------------------------------------------------
extern "C" void kernel_launch(void* const* d_in, const int* in_sizes, int n_in,
                              void* d_out, int out_size) {
    const float* h   = (const float*)d_in[0];
    const int*   ei  = (const int*)d_in[1];
    const float* ef  = (const float*)d_in[2];
    const float* Wn  = (const float*)d_in[3];
    const float* We  = (const float*)d_in[4];
    const float* Asw = (const float*)d_in[5];
    const float* Adw = (const float*)d_in[6];
    const float* Wm  = (const float*)d_in[7];
    float* out = (float*)d_out;

    k_prep<<<PREP_INIT_BLOCKS + PREP_CVTW_BLOCKS + PREP_COEF_BLOCKS, 256>>>(
        out, Wm, Wn, Asw, Adw);
    k_sgemm<<<(N_NODES + 127) / 128, 256>>>(h);
    k_mid<<<GEMM_BLOCKS + E_EDGES / 512, 256>>>(ei, ef, We);
    k_out<<<2960, 256>>>(ei, ef, Wm, out);
}

// round 17
// speedup vs baseline: 2.1108x; 1.0515x over previous
#include <cuda_runtime.h>
#include <cuda_fp16.h>
#include <mma.h>
#include <math.h>

using namespace nvcuda;

#define N_NODES 40000
#define E_EDGES 640000
#define IN_F 128
#define OUT_F 32
#define HEADS 8
#define MCOLS (HEADS * OUT_F)   // 256
#define NPAD 128                // row padding (sgemm tail block)
#define GEMM_BLOCKS 625         // k_mid: blocks [0,625) = gemm, rest = score

// prep-kernel block partition
#define PREP_INIT_BLOCKS 5000   // 5000*256 = 1.28M >= N*32, N*8
#define PREP_CVTW_BLOCKS 64     // 64*256*2 floats = 32768
#define PREP_COEF_BLOCKS 4      // 4*256 = 1024 (i,h) pairs

// Scratch (static device globals; no allocation allowed).
__device__ __align__(16) __half g_Mh[N_NODES * MCOLS];           // h @ W_msg[:128] fp16
__device__ __align__(16) __half g_h16[(N_NODES + NPAD) * IN_F];  // h in fp16
__device__ __align__(16) __half g_W16[IN_F * MCOLS];             // W_msg[:128] fp16
__device__ __align__(32) __half g_C16[IN_F * 16];                // [csrc | cdst] fp16
__device__ __align__(16) float g_asrc[N_NODES * HEADS];
__device__ __align__(16) float g_adst[N_NODES * HEADS];
__device__ __align__(16) float g_sum[N_NODES * HEADS];   // softmax denominators
__device__ __align__(16) float g_attn[E_EDGES * HEADS];  // exp(score), edge order

// ---------------------------------------------------------------------------
// fused prep: [0,5000) zero out+g_sum; [5000,5064) cvt W_msg; [5064,5068) coef
__global__ void __launch_bounds__(256) k_prep(float* __restrict__ out,
                                              const float* __restrict__ Wm,
                                              const float* __restrict__ Wn,
                                              const float* __restrict__ att_s,
                                              const float* __restrict__ att_d) {
    int b = blockIdx.x;
    if (b < PREP_INIT_BLOCKS) {
        int i = b * 256 + threadIdx.x;
        if (i < N_NODES * OUT_F) out[i] = 0.f;
        if (i < N_NODES * HEADS) g_sum[i] = 0.f;
    } else if (b < PREP_INIT_BLOCKS + PREP_CVTW_BLOCKS) {
        int i = (b - PREP_INIT_BLOCKS) * 256 + threadIdx.x;   // 0..16383
        float2 v = *(const float2*)(Wm + i * 2);
        *(__half2*)(g_W16 + i * 2) = __floats2half2_rn(v.x, v.y);
    } else {
        int t = (b - PREP_INIT_BLOCKS - PREP_CVTW_BLOCKS) * 256 + threadIdx.x;
        int i = t >> 3, hh = t & 7;
        float s1 = 0.f, s2 = 0.f;
        #pragma unroll
        for (int f = 0; f < OUT_F; f++) {
            float w = Wn[i * MCOLS + hh * OUT_F + f];
            s1 += w * att_s[hh * OUT_F + f];
            s2 += w * att_d[hh * OUT_F + f];
        }
        g_C16[i * 16 + hh]     = __float2half_rn(s1);
        g_C16[i * 16 + 8 + hh] = __float2half_rn(s2);
    }
}

// ---------------------------------------------------------------------------
// fused h-convert + pre-score GEMM. Block = 128 rows: convert fp32->fp16 into
// smem AND g_h16, then [asrc|adst] = Hs @ C16 via wmma.
__global__ void __launch_bounds__(256) k_sgemm(const float* __restrict__ h) {
    __shared__ __align__(16) __half Hs[128][128];     // 32 KB
    __shared__ __align__(16) float Cst[8][16][16];
    int tid = threadIdx.x;
    int n0 = blockIdx.x * 128;
    #pragma unroll
    for (int q = 0; q < 8; q++) {
        int idx = q * 2048 + tid * 8;     // flat elem idx, 8 floats per thread
        int r = idx >> 7, c = idx & 127;
        int grow = n0 + r;
        __half2 t16[4];
        if (grow < N_NODES) {
            const float* p = h + (size_t)grow * IN_F + c;
            float4 a = *(const float4*)p;
            float4 bb = *(const float4*)(p + 4);
            t16[0] = __floats2half2_rn(a.x, a.y);
            t16[1] = __floats2half2_rn(a.z, a.w);
            t16[2] = __floats2half2_rn(bb.x, bb.y);
            t16[3] = __floats2half2_rn(bb.z, bb.w);
            *(uint4*)(g_h16 + (size_t)grow * IN_F + c) = *(uint4*)t16;
        } else {
            t16[0] = t16[1] = t16[2] = t16[3] = __half2half2(__float2half(0.f));
        }
        *(uint4*)&Hs[r][c] = *(uint4*)t16;
    }
    __syncthreads();
    int wid = tid >> 5, lane = tid & 31;
    int row0 = wid * 16;
    wmma::fragment<wmma::accumulator, 16, 16, 16, float> c;
    wmma::fill_fragment(c, 0.f);
    #pragma unroll
    for (int k0 = 0; k0 < IN_F; k0 += 16) {
        wmma::fragment<wmma::matrix_a, 16, 16, 16, __half, wmma::row_major> a;
        wmma::fragment<wmma::matrix_b, 16, 16, 16, __half, wmma::row_major> b;
        wmma::load_matrix_sync(a, &Hs[row0][k0], 128);
        wmma::load_matrix_sync(b, g_C16 + k0 * 16, 16);
        wmma::mma_sync(c, a, b, c);
    }
    wmma::store_matrix_sync(&Cst[wid][0][0], c, 16, wmma::mem_row_major);
    __syncwarp();
    if (lane < 16) {
        int n = n0 + row0 + lane;
        if (n < N_NODES) {
            const float4* p = (const float4*)&Cst[wid][lane][0];
            *(float4*)&g_asrc[n * HEADS]     = p[0];
            *(float4*)&g_asrc[n * HEADS + 4] = p[1];
            *(float4*)&g_adst[n * HEADS]     = p[2];
            *(float4*)&g_adst[n * HEADS + 4] = p[3];
        }
    }
}

// ---------------------------------------------------------------------------
// FUSED mid kernel: blocks [0,GEMM_BLOCKS) run the M-GEMM; remaining 1250
// blocks run the score pass with 2 edges/thread (e and e+E/2) for MLP.
__global__ void __launch_bounds__(256) k_mid(const int* __restrict__ ei,
                                             const float* __restrict__ ef,
                                             const float* __restrict__ We) {
    if (blockIdx.x < GEMM_BLOCKS) {
        __shared__ __align__(32) __half Ah[64][48];
        __shared__ __align__(32) __half Bh[32][272];
        __shared__ __align__(16) float Cst[8][16][16];
        int tid = threadIdx.x;
        int wid = tid >> 5, lane = tid & 31;
        int wm = wid >> 2;
        int wn = wid & 3;
        int m0 = blockIdx.x * 64;

        wmma::fragment<wmma::accumulator, 16, 16, 16, float> c[2][4];
        #pragma unroll
        for (int i = 0; i < 2; i++)
            #pragma unroll
            for (int j = 0; j < 4; j++) wmma::fill_fragment(c[i][j], 0.f);

        int ar = tid >> 2;               // 0..63
        int ac = (tid & 3) * 8;          // halves
        int br = tid >> 3;               // 0..31
        int bc = (tid & 7) * 32;         // halves

        for (int k0 = 0; k0 < IN_F; k0 += 32) {
            *(uint4*)&Ah[ar][ac] =
                *(const uint4*)(g_h16 + (size_t)(m0 + ar) * IN_F + k0 + ac);
            const __half* bg = g_W16 + (size_t)(k0 + br) * MCOLS + bc;
            #pragma unroll
            for (int q = 0; q < 4; q++)
                *(uint4*)&Bh[br][bc + q * 8] = *(const uint4*)(bg + q * 8);
            __syncthreads();
            #pragma unroll
            for (int kk = 0; kk < 32; kk += 16) {
                wmma::fragment<wmma::matrix_a, 16, 16, 16, __half, wmma::row_major> af[2];
                wmma::fragment<wmma::matrix_b, 16, 16, 16, __half, wmma::row_major> bf[4];
                #pragma unroll
                for (int i = 0; i < 2; i++)
                    wmma::load_matrix_sync(af[i], &Ah[wm * 32 + i * 16][kk], 48);
                #pragma unroll
                for (int j = 0; j < 4; j++)
                    wmma::load_matrix_sync(bf[j], &Bh[kk][wn * 64 + j * 16], 272);
                #pragma unroll
                for (int i = 0; i < 2; i++)
                    #pragma unroll
                    for (int j = 0; j < 4; j++)
                        wmma::mma_sync(c[i][j], af[i], bf[j], c[i][j]);
            }
            __syncthreads();
        }
        int rr = lane >> 1, cc = (lane & 1) * 8;
        #pragma unroll
        for (int i = 0; i < 2; i++)
            #pragma unroll
            for (int j = 0; j < 4; j++) {
                wmma::store_matrix_sync(&Cst[wid][0][0], c[i][j], 16, wmma::mem_row_major);
                __syncwarp();
                const float* sp = &Cst[wid][rr][cc];
                __half2 hv[4];
                #pragma unroll
                for (int q = 0; q < 4; q++)
                    hv[q] = __floats2half2_rn(sp[q * 2], sp[q * 2 + 1]);
                int grow = m0 + wm * 32 + i * 16 + rr;
                int gcol = wn * 64 + j * 16 + cc;
                *(uint4*)(g_Mh + (size_t)grow * MCOLS + gcol) = *(uint4*)hv;
                __syncwarp();
            }
    } else {
        // score: 2 independent edges per thread for MLP
        int base = (blockIdx.x - GEMM_BLOCKS) * 256 + threadIdx.x;
        int ee[2] = {base, base + E_EDGES / 2};
        int s[2], d[2];
        float x[2];
        #pragma unroll
        for (int u = 0; u < 2; u++) {
            s[u] = ei[ee[u]];
            d[u] = ei[E_EDGES + ee[u]];
            x[u] = ef[ee[u]];
        }
        float4 sa0[2], sa1[2], da0[2], da1[2];
        #pragma unroll
        for (int u = 0; u < 2; u++) {
            sa0[u] = *(const float4*)&g_asrc[s[u] * HEADS];
            sa1[u] = *(const float4*)&g_asrc[s[u] * HEADS + 4];
            da0[u] = *(const float4*)&g_adst[d[u] * HEADS];
            da1[u] = *(const float4*)&g_adst[d[u] * HEADS + 4];
        }
        #pragma unroll
        for (int u = 0; u < 2; u++) {
            float sv[8] = {sa0[u].x, sa0[u].y, sa0[u].z, sa0[u].w,
                           sa1[u].x, sa1[u].y, sa1[u].z, sa1[u].w};
            float dv[8] = {da0[u].x, da0[u].y, da0[u].z, da0[u].w,
                           da1[u].x, da1[u].y, da1[u].z, da1[u].w};
            float p[8];
            #pragma unroll
            for (int hh = 0; hh < HEADS; hh++) {
                float a = sv[hh] + dv[hh] + x[u] * __ldg(&We[hh]);
                a = (a > 0.f) ? a : 0.2f * a;          // leaky relu
                p[hh] = __expf(a);
            }
            float* ap = &g_attn[(size_t)ee[u] * HEADS];
            *(float4*)ap       = make_float4(p[0], p[1], p[2], p[3]);
            *(float4*)(ap + 4) = make_float4(p[4], p[5], p[6], p[7]);
            float* sp = &g_sum[d[u] * HEADS];
            asm volatile("red.global.add.v4.f32 [%0], {%1, %2, %3, %4};"
                         :: "l"(sp), "f"(p[0]), "f"(p[1]), "f"(p[2]), "f"(p[3])
                         : "memory");
            asm volatile("red.global.add.v4.f32 [%0], {%1, %2, %3, %4};"
                         :: "l"(sp + 4), "f"(p[4]), "f"(p[5]), "f"(p[6]), "f"(p[7])
                         : "memory");
        }
    }
}

// ---------------------------------------------------------------------------
// final pass v4: 8 lanes per edge, 4 edges per group-iteration (MLP x4),
// W row cached in SMEM (frees 32 regs -> higher occupancy).
__global__ void __launch_bounds__(256) k_out(const int* __restrict__ ei,
                                             const float* __restrict__ ef,
                                             const float* __restrict__ Wm,
                                             float* __restrict__ out) {
    __shared__ float Ws[MCOLS];        // W_msg row 128 (edge-feat row)
    int tid = threadIdx.x;
    Ws[tid] = __ldg(Wm + (size_t)IN_F * MCOLS + tid);   // 256 threads exact
    __syncthreads();

    int lane = tid & 31;
    int g = lane >> 3;               // edge slot within warp (0..3)
    int i = lane & 7;                // feature cluster (4 feats)
    const float* Wl = Ws + i * 4;    // Wl[hh*32 .. +3] via LDS.128

    int warpId = (blockIdx.x * blockDim.x + tid) >> 5;
    int nWarps = (gridDim.x * blockDim.x) >> 5;

    for (int e16 = warpId; e16 < E_EDGES / 16; e16 += nWarps) {
        int e[4], s[4], d[4];
        float x[4], al[4];
        #pragma unroll
        for (int u = 0; u < 4; u++) {
            e[u] = e16 * 16 + u * 4 + g;
            s[u] = ei[e[u]];
            d[u] = ei[E_EDGES + e[u]];
            x[u] = ef[e[u]];
        }
        #pragma unroll
        for (int u = 0; u < 4; u++) {
            float sm = g_sum[d[u] * HEADS + i];
            al[u] = __fdividef(g_attn[(size_t)e[u] * HEADS + i],
                               fmaxf(sm, 1e-12f));
        }
        float acc[4][4];
        #pragma unroll
        for (int u = 0; u < 4; u++)
            #pragma unroll
            for (int j = 0; j < 4; j++) acc[u][j] = 0.f;

        #pragma unroll
        for (int hh = 0; hh < HEADS; hh++) {
            float4 w = *(const float4*)(Wl + hh * OUT_F);
            #pragma unroll
            for (int u = 0; u < 4; u++) {
                float a = __shfl_sync(0xffffffffu, al[u], g * 8 + hh);
                uint2 mv = *(const uint2*)(g_Mh + (size_t)s[u] * MCOLS +
                                           hh * OUT_F + i * 4);
                float2 m0 = __half22float2(*(__half2*)&mv.x);
                float2 m1 = __half22float2(*(__half2*)&mv.y);
                acc[u][0] = fmaf(a, fmaf(x[u], w.x, m0.x), acc[u][0]);
                acc[u][1] = fmaf(a, fmaf(x[u], w.y, m0.y), acc[u][1]);
                acc[u][2] = fmaf(a, fmaf(x[u], w.z, m1.x), acc[u][2]);
                acc[u][3] = fmaf(a, fmaf(x[u], w.w, m1.y), acc[u][3]);
            }
        }
        #pragma unroll
        for (int u = 0; u < 4; u++) {
            float* op = out + (size_t)d[u] * OUT_F + i * 4;   // 16B aligned
            asm volatile("red.global.add.v4.f32 [%0], {%1, %2, %3, %4};"
                         :: "l"(op), "f"(acc[u][0] * 0.125f),
                            "f"(acc[u][1] * 0.125f), "f"(acc[u][2] * 0.125f),
                            "f"(acc[u][3] * 0.125f) : "memory");
        }
    }
}

// ---------------------------------------------------------------------------
extern "C" void kernel_launch(void* const* d_in, const int* in_sizes, int n_in,
                              void* d_out, int out_size) {
    const float* h   = (const float*)d_in[0];
    const int*   ei  = (const int*)d_in[1];
    const float* ef  = (const float*)d_in[2];
    const float* Wn  = (const float*)d_in[3];
    const float* We  = (const float*)d_in[4];
    const float* Asw = (const float*)d_in[5];
    const float* Adw = (const float*)d_in[6];
    const float* Wm  = (const float*)d_in[7];
    float* out = (float*)d_out;

    k_prep<<<PREP_INIT_BLOCKS + PREP_CVTW_BLOCKS + PREP_COEF_BLOCKS, 256>>>(
        out, Wm, Wn, Asw, Adw);
    k_sgemm<<<(N_NODES + 127) / 128, 256>>>(h);
    k_mid<<<GEMM_BLOCKS + E_EDGES / 512, 256>>>(ei, ef, We);
    k_out<<<2960, 256>>>(ei, ef, Wm, out);
}